// round 12
// baseline (speedup 1.0000x reference)
#include <cuda_runtime.h>
#include <cuda_bf16.h>
#include <cuda_fp16.h>
#include <math.h>
#include <stdint.h>

#define D_MODEL 512
#define N_TOK   1024
#define BATCH   2
#define HEADS   8
#define HIDDEN  2048
#define M_ROWS  (BATCH * N_TOK)   // 2048
#define LOG2E 1.4426950408889634f

// ---------------- scratch (static device globals; no allocation) ----------------
__device__ __align__(256) __half g_xln16[M_ROWS * D_MODEL];                 // LN out fp16
__device__ __align__(256) __nv_bfloat16 g_qp [M_ROWS * D_MODEL];            // Q bf16 pre-scaled
__device__ __align__(256) __nv_bfloat16 g_kp [BATCH * HEADS * N_TOK * 64];  // K [bh][key][d]
__device__ __align__(256) __nv_bfloat16 g_vtp[BATCH * HEADS * 64 * N_TOK];  // V^T [bh][d][key]
__device__ __align__(256) __half g_att16[M_ROWS * D_MODEL];                 // attn out fp16
__device__ __align__(256) float  g_x2 [M_ROWS * D_MODEL];
__device__ __align__(256) __half g_hid16[M_ROWS * HIDDEN];
// transposed fp16 weights [N][K]
__device__ __align__(256) __half g_wqkv_t[1536 * 512];
__device__ __align__(256) __half g_wout_t[512 * 512];
__device__ __align__(256) __half g_w1_t  [2048 * 512];
__device__ __align__(256) __half g_w2_t  [512 * 2048];

// ---------------- helpers --------------------------------------------------------
__device__ __forceinline__ void cp16(uint32_t smem, const void* g) {
    asm volatile("cp.async.cg.shared.global [%0], [%1], 16;" :: "r"(smem), "l"(g));
}
__device__ __forceinline__ void cp_commit() { asm volatile("cp.async.commit_group;"); }
template<int N> __device__ __forceinline__ void cp_wait() {
    asm volatile("cp.async.wait_group %0;" :: "n"(N));
}
__device__ __forceinline__ uint32_t pkbf(float a, float b) {
    __nv_bfloat162 h = __floats2bfloat162_rn(a, b);
    return *(uint32_t*)&h;
}
__device__ __forceinline__ uint32_t pkhf(float a, float b) {
    __half2 h = __floats2half2_rn(a, b);
    return *(uint32_t*)&h;
}
__device__ __forceinline__ uint32_t ex2bf(uint32_t x) {
    uint32_t r; asm("ex2.approx.ftz.bf16x2 %0, %1;" : "=r"(r) : "r"(x)); return r;
}
__device__ __forceinline__ void mma_f16(float c[4], const uint32_t a[4], const uint32_t b[2]) {
    asm volatile(
        "mma.sync.aligned.m16n8k16.row.col.f32.f16.f16.f32 "
        "{%0,%1,%2,%3}, {%4,%5,%6,%7}, {%8,%9}, {%0,%1,%2,%3};"
        : "+f"(c[0]), "+f"(c[1]), "+f"(c[2]), "+f"(c[3])
        : "r"(a[0]), "r"(a[1]), "r"(a[2]), "r"(a[3]), "r"(b[0]), "r"(b[1]));
}
__device__ __forceinline__ void mma_bf16(float c[4], const uint32_t a[4], const uint32_t b[2]) {
    asm volatile(
        "mma.sync.aligned.m16n8k16.row.col.f32.bf16.bf16.f32 "
        "{%0,%1,%2,%3}, {%4,%5,%6,%7}, {%8,%9}, {%0,%1,%2,%3};"
        : "+f"(c[0]), "+f"(c[1]), "+f"(c[2]), "+f"(c[3])
        : "r"(a[0]), "r"(a[1]), "r"(a[2]), "r"(a[3]), "r"(b[0]), "r"(b[1]));
}
__device__ __forceinline__ void ldmx4(uint32_t r[4], uint32_t addr) {
    asm volatile("ldmatrix.sync.aligned.m8n8.x4.shared.b16 {%0,%1,%2,%3}, [%4];"
                 : "=r"(r[0]), "=r"(r[1]), "=r"(r[2]), "=r"(r[3]) : "r"(addr));
}
__device__ __forceinline__ float sqrt_approx(float x) {
    float r; asm("sqrt.approx.f32 %0, %1;" : "=f"(r) : "f"(x)); return r;
}

// ---------------- weight pack: fp32 [K][N] -> fp16 [N][K] ------------------------
__global__ void pack_weights(const float* __restrict__ wqkv, const float* __restrict__ wout,
                             const float* __restrict__ w1, const float* __restrict__ w2,
                             __half* __restrict__ wqkv_t, __half* __restrict__ wout_t,
                             __half* __restrict__ w1_t, __half* __restrict__ w2_t) {
    __shared__ float tile[64][65];
    const int bx = blockIdx.x, tid = threadIdx.x;
    const float* src; __half* dst; int K, N, tk, tn;
    if (bx < 192)      { src = wqkv; dst = wqkv_t; K = 512;  N = 1536; int t = bx;       tk = t & 7;  tn = t >> 3; }
    else if (bx < 256) { src = wout; dst = wout_t; K = 512;  N = 512;  int t = bx - 192; tk = t & 7;  tn = t >> 3; }
    else if (bx < 512) { src = w1;   dst = w1_t;   K = 512;  N = 2048; int t = bx - 256; tk = t & 7;  tn = t >> 3; }
    else               { src = w2;   dst = w2_t;   K = 2048; N = 512;  int t = bx - 512; tk = t & 31; tn = t >> 5; }
    const int k0 = tk * 64, n0 = tn * 64;

    #pragma unroll
    for (int u = 0; u < 4; u++) {
        int f = tid + u * 256;
        int kr = f >> 4, nc = (f & 15) * 4;
        float4 v = *(const float4*)(src + (size_t)(k0 + kr) * N + n0 + nc);
        tile[nc + 0][kr] = v.x;
        tile[nc + 1][kr] = v.y;
        tile[nc + 2][kr] = v.z;
        tile[nc + 3][kr] = v.w;
    }
    __syncthreads();
    #pragma unroll
    for (int u = 0; u < 2; u++) {
        int f = tid + u * 256;
        int nr = f >> 3, kc = (f & 7) * 8;
        uint4 o;
        o.x = pkhf(tile[nr][kc + 0], tile[nr][kc + 1]);
        o.y = pkhf(tile[nr][kc + 2], tile[nr][kc + 3]);
        o.z = pkhf(tile[nr][kc + 4], tile[nr][kc + 5]);
        o.w = pkhf(tile[nr][kc + 6], tile[nr][kc + 7]);
        *(uint4*)(dst + (size_t)(n0 + nr) * K + k0 + kc) = o;
    }
}

// ---------------- LayerNorm (fp32 in, fp16 out) ----------------------------------
__global__ void ln_kernel(const float* __restrict__ x, const float* __restrict__ g,
                          const float* __restrict__ b, __half* __restrict__ y) {
    int row = blockIdx.x;
    const float* xr = x + (size_t)row * D_MODEL;
    int t = threadIdx.x;
    float v0 = xr[t];
    float v1 = xr[t + 256];

    __shared__ float sh[8], sh2[8];
    int w = t >> 5, lane = t & 31;

    float s = v0 + v1;
    #pragma unroll
    for (int o = 16; o; o >>= 1) s += __shfl_xor_sync(0xffffffffu, s, o);
    if (lane == 0) sh[w] = s;
    __syncthreads();
    float mean = (sh[0]+sh[1]+sh[2]+sh[3]+sh[4]+sh[5]+sh[6]+sh[7]) * (1.0f / D_MODEL);

    float d0 = v0 - mean, d1 = v1 - mean;
    float q = d0 * d0 + d1 * d1;
    #pragma unroll
    for (int o = 16; o; o >>= 1) q += __shfl_xor_sync(0xffffffffu, q, o);
    if (lane == 0) sh2[w] = q;
    __syncthreads();
    float var = (sh2[0]+sh2[1]+sh2[2]+sh2[3]+sh2[4]+sh2[5]+sh2[6]+sh2[7]) * (1.0f / D_MODEL);
    float inv = rsqrtf(var + 1e-5f);

    __half* yr = y + (size_t)row * D_MODEL;
    yr[t]       = __float2half(d0 * inv * g[t]       + b[t]);
    yr[t + 256] = __float2half(d1 * inv * g[t + 256] + b[t + 256]);
}

// ---------------- fp16 GEMM mainloop (attention-schema fragments) ----------------
#define GEMM16_BODY(A_, Bt_, K_)                                                   \
    constexpr int WM = BM / 2;                                                     \
    constexpr int MT = WM / 16;                                                    \
    extern __shared__ char smc[];                                                  \
    const uint32_t S0 = (uint32_t)__cvta_generic_to_shared(smc);                   \
    const uint32_t OAS = S0;                                                       \
    const uint32_t OBS = S0 + 2 * BM * 128;                                        \
    const int tid  = threadIdx.x;                                                  \
    const int warp = tid >> 5;                                                     \
    const int lane = tid & 31;                                                     \
    const int gpid = lane >> 2;                                                    \
    const int tgid = lane & 3;                                                     \
    const int l7   = lane & 7;                                                     \
    const int sel  = lane >> 3;                                                    \
    const int wm = warp >> 1;                                                      \
    const int wn = warp & 1;                                                       \
    const int m0 = blockIdx.y * BM;                                                \
    const int n0 = blockIdx.x * 64;                                                \
    float acc[MT][4][4];                                                           \
    _Pragma("unroll")                                                              \
    for (int i = 0; i < MT; i++)                                                   \
        _Pragma("unroll")                                                          \
        for (int j = 0; j < 4; j++)                                                \
            _Pragma("unroll")                                                      \
            for (int e = 0; e < 4; e++) acc[i][j][e] = 0.0f;                       \
    auto loadA = [&](int buf, int k0) {                                            \
        _Pragma("unroll")                                                          \
        for (int u = 0; u < BM / 16; u++) {                                        \
            int r = (tid >> 3) + u * 16; int g = tid & 7;                          \
            cp16(OAS + (uint32_t)(buf * BM * 128 + r * 128 + ((g ^ (r & 7)) << 4)),\
                 A_ + (size_t)(m0 + r) * K_ + k0 + g * 8);                         \
        }                                                                          \
    };                                                                             \
    auto loadB = [&](int buf, int k0) {                                            \
        _Pragma("unroll")                                                          \
        for (int u = 0; u < 4; u++) {                                              \
            int r = (tid >> 3) + u * 16; int g = tid & 7;                          \
            cp16(OBS + (uint32_t)(buf * 8192 + r * 128 + ((g ^ (r & 7)) << 4)),    \
                 Bt_ + (size_t)(n0 + r) * K_ + k0 + g * 8);                        \
        }                                                                          \
    };                                                                             \
    const int tiles = K_ >> 6;                                                     \
    loadA(0, 0); loadB(0, 0); cp_commit();                                         \
    for (int kt = 0; kt < tiles; kt++) {                                           \
        const int cbuf = kt & 1;                                                   \
        if (kt + 1 < tiles) {                                                      \
            loadA(cbuf ^ 1, (kt + 1) * 64);                                        \
            loadB(cbuf ^ 1, (kt + 1) * 64);                                        \
            cp_commit(); cp_wait<1>();                                             \
        } else { cp_wait<0>(); }                                                   \
        __syncthreads();                                                           \
        _Pragma("unroll")                                                          \
        for (int ks = 0; ks < 4; ks++) {                                           \
            uint32_t af[MT][4];                                                    \
            _Pragma("unroll")                                                      \
            for (int mt = 0; mt < MT; mt++) {                                      \
                int row = wm * WM + mt * 16 + l7 + ((sel & 1) << 3);               \
                int chunk = 2 * ks + (sel >> 1);                                   \
                ldmx4(af[mt], OAS + (uint32_t)(cbuf * BM * 128 + row * 128 +       \
                                               ((chunk ^ (row & 7)) << 4)));       \
            }                                                                      \
            uint32_t bf2[2][4];                                                    \
            _Pragma("unroll")                                                      \
            for (int np = 0; np < 2; np++) {                                       \
                int row = wn * 32 + np * 16 + l7 + ((sel >> 1) << 3);              \
                int chunk = 2 * ks + (sel & 1);                                    \
                ldmx4(bf2[np], OBS + (uint32_t)(cbuf * 8192 + row * 128 +          \
                                                ((chunk ^ (row & 7)) << 4)));      \
            }                                                                      \
            _Pragma("unroll")                                                      \
            for (int mt = 0; mt < MT; mt++) {                                      \
                mma_f16(acc[mt][0], af[mt], bf2[0]);                               \
                mma_f16(acc[mt][1], af[mt], bf2[0] + 2);                           \
                mma_f16(acc[mt][2], af[mt], bf2[1]);                               \
                mma_f16(acc[mt][3], af[mt], bf2[1] + 2);                           \
            }                                                                      \
        }                                                                          \
        __syncthreads();                                                           \
    }

// ---------------- generic fp16 GEMM (bias; optional gelu/residual; f32/f16 out) --
template<int BM, int OUTF16>
__global__ void __launch_bounds__(128) gemm_f16(
        const __half* __restrict__ A, const __half* __restrict__ Bt,
        const float* __restrict__ bias, const float* __restrict__ res,
        void* __restrict__ Cout, int M, int Nn, int K, int do_gelu) {
    GEMM16_BODY(A, Bt, K)

    #pragma unroll
    for (int mt = 0; mt < MT; mt++) {
        #pragma unroll
        for (int nt = 0; nt < 4; nt++) {
            int r0 = m0 + wm * WM + mt * 16 + gpid;
            int c0 = n0 + wn * 32 + nt * 8 + 2 * tgid;
            float bb0 = bias[c0], bb1 = bias[c0 + 1];
            float v00 = acc[mt][nt][0] + bb0, v01 = acc[mt][nt][1] + bb1;
            float v10 = acc[mt][nt][2] + bb0, v11 = acc[mt][nt][3] + bb1;
            if (do_gelu) {
                v00 = 0.5f * v00 * (1.0f + erff(v00 * 0.70710678118654752f));
                v01 = 0.5f * v01 * (1.0f + erff(v01 * 0.70710678118654752f));
                v10 = 0.5f * v10 * (1.0f + erff(v10 * 0.70710678118654752f));
                v11 = 0.5f * v11 * (1.0f + erff(v11 * 0.70710678118654752f));
            }
            if (res) {
                v00 += res[(size_t)r0 * Nn + c0];
                v01 += res[(size_t)r0 * Nn + c0 + 1];
                v10 += res[(size_t)(r0 + 8) * Nn + c0];
                v11 += res[(size_t)(r0 + 8) * Nn + c0 + 1];
            }
            if (OUTF16) {
                __half* C = (__half*)Cout;
                *(uint32_t*)(C + (size_t)r0 * Nn + c0)       = pkhf(v00, v01);
                *(uint32_t*)(C + (size_t)(r0 + 8) * Nn + c0) = pkhf(v10, v11);
            } else {
                float* C = (float*)Cout;
                *(float2*)(C + (size_t)r0 * Nn + c0)       = make_float2(v00, v01);
                *(float2*)(C + (size_t)(r0 + 8) * Nn + c0) = make_float2(v10, v11);
            }
        }
    }
}

// ---------------- QKV fp16 GEMM with fused bf16 pack epilogue --------------------
__global__ void __launch_bounds__(128) gemm_qkv(
        const __half* __restrict__ A, const __half* __restrict__ Bt,
        const float* __restrict__ bias,
        __nv_bfloat16* __restrict__ qp, __nv_bfloat16* __restrict__ kp,
        __nv_bfloat16* __restrict__ vtp, int Nn, int K) {
    constexpr int BM = 128;
    GEMM16_BODY(A, Bt, K)

    const int region = n0 / 512;
    const int h = (n0 % 512) / 64;
    #pragma unroll
    for (int mt = 0; mt < MT; mt++) {
        #pragma unroll
        for (int nt = 0; nt < 4; nt++) {
            int r0 = m0 + wm * WM + mt * 16 + gpid;
            int lc = wn * 32 + nt * 8 + 2 * tgid;
            int c0 = n0 + lc;
            float bb0 = bias[c0], bb1 = bias[c0 + 1];
            float v00 = acc[mt][nt][0] + bb0, v01 = acc[mt][nt][1] + bb1;
            float v10 = acc[mt][nt][2] + bb0, v11 = acc[mt][nt][3] + bb1;
            int bb_ = r0 >> 10, key = r0 & 1023;
            int bh  = bb_ * HEADS + h;
            if (region == 0) {
                const float qs = 0.125f * LOG2E;
                size_t a0 = (size_t)(bb_ * N_TOK + key) * D_MODEL + h * 64 + lc;
                *(uint32_t*)(qp + a0)                 = pkbf(v00 * qs, v01 * qs);
                *(uint32_t*)(qp + a0 + 8 * D_MODEL)   = pkbf(v10 * qs, v11 * qs);
            } else if (region == 1) {
                size_t a0 = (size_t)(bh * N_TOK + key) * 64 + lc;
                *(uint32_t*)(kp + a0)        = pkbf(v00, v01);
                *(uint32_t*)(kp + a0 + 512)  = pkbf(v10, v11);
            } else {
                size_t a0 = (size_t)(bh * 64 + lc) * N_TOK + key;
                vtp[a0]              = __float2bfloat16(v00);
                vtp[a0 + N_TOK]      = __float2bfloat16(v01);
                vtp[a0 + 8]          = __float2bfloat16(v10);
                vtp[a0 + N_TOK + 8]  = __float2bfloat16(v11);
            }
        }
    }
}

// ---------------- bf16 mma flash attention, split-KV warp groups -----------------
// 256 threads = 8 warps. Warps 0-3 (group A) process keys [0,32) of each 64-key
// tile; warps 4-7 (group B) keys [32,64). No-max exp2 softmax makes the final
// cross-group merge an exact sum: O = O_A + O_B, l = l_A + l_B (smem, once).
// smem: Ks[2][8KB]@0, Vs[2][8KB]@16384, Q-stage+P-slices 16KB@32768,
//       kc[2][512B]@49152 => 50176 B. Merge reuses bytes 0..17408 after mainloop.
__global__ void __launch_bounds__(256) attn_bf16(
        const __nv_bfloat16* __restrict__ qp, const __nv_bfloat16* __restrict__ kp,
        const __nv_bfloat16* __restrict__ vtp, const float* __restrict__ coords,
        const float* __restrict__ w_edge, __half* __restrict__ out) {
    extern __shared__ char smb[];
    const uint32_t S0 = (uint32_t)__cvta_generic_to_shared(smb);
    const uint32_t OKS = S0, OVS = S0 + 16384, OPS = S0 + 32768;
    const uint32_t OKC = S0 + 49152;

    const int b = blockIdx.z, h = blockIdx.y, n0 = blockIdx.x * 64;
    const int bh = b * HEADS + h;
    const int tid = threadIdx.x, warp = tid >> 5, lane = tid & 31;
    const int kgrp = warp >> 2, wq = warp & 3;
    const int g = lane >> 2, t = lane & 3;
    const int l7 = lane & 7, sel = lane >> 3;
    const float we2 = w_edge[2 * HEADS + h] * LOG2E;

    const uint32_t bone = (lane < 4) ? 0x3F803F80u : 0u;
    const uint32_t bones[2] = {bone, bone};

    auto issue = [&](int buf, int m0) {
        #pragma unroll
        for (int u = 0; u < 2; u++) {
            int f = tid + u * 256; int r = f >> 3; int c = f & 7;
            uint32_t off = (uint32_t)(buf * 8192 + r * 128 + ((c ^ (r & 7)) << 4));
            cp16(OKS + off, kp  + (size_t)(bh * N_TOK + m0 + r) * 64 + c * 8);
            cp16(OVS + off, vtp + (size_t)(bh * 64 + r) * N_TOK + m0 + c * 8);
        }
        if (tid < 32)
            cp16(OKC + (uint32_t)(buf * 512 + tid * 16),
                 coords + (size_t)(b * N_TOK + m0) * 2 + tid * 4);
    };

    issue(0, 0);
    #pragma unroll
    for (int u = 0; u < 2; u++) {
        int f = tid + u * 256; int r = f >> 3; int c = f & 7;
        cp16(OPS + (uint32_t)(r * 128 + ((c ^ (r & 7)) << 4)),
             qp + (size_t)(b * N_TOK + n0 + r) * D_MODEL + h * 64 + c * 8);
    }
    cp_commit();

    const int qr0 = n0 + wq * 16 + g;
    float2 qc0 = *(const float2*)(coords + (size_t)(b * N_TOK + qr0) * 2);
    float2 qc1 = *(const float2*)(coords + (size_t)(b * N_TOK + qr0 + 8) * 2);

    cp_wait<0>();
    __syncthreads();

    uint32_t Qf[4][4];
    {
        const int row = wq * 16 + l7 + ((sel & 1) << 3);
        #pragma unroll
        for (int ks = 0; ks < 4; ks++) {
            int chunk = 2 * ks + (sel >> 1);
            ldmx4(Qf[ks], OPS + (uint32_t)(row * 128 + ((chunk ^ (row & 7)) << 4)));
        }
    }

    float O[8][4];
    #pragma unroll
    for (int nt = 0; nt < 8; nt++)
        #pragma unroll
        for (int e = 0; e < 4; e++) O[nt][e] = 0.0f;
    float Ox[4] = {0.0f, 0.0f, 0.0f, 0.0f};

    for (int it = 0; it < 16; it++) {
        const int buf = it & 1;
        if (it + 1 < 16) { issue(buf ^ 1, (it + 1) * 64); cp_commit(); cp_wait<1>(); }
        else cp_wait<0>();
        __syncthreads();   // also orders Qf extraction (it=0) before P-slice writes

        const float* kcb = (const float*)(smb + 49152 + buf * 512);

        // S = Q @ K^T over this group's 32 keys
        float S[4][4];
        #pragma unroll
        for (int nt = 0; nt < 4; nt++)
            #pragma unroll
            for (int e = 0; e < 4; e++) S[nt][e] = 0.0f;
        #pragma unroll
        for (int ks = 0; ks < 4; ks++) {
            #pragma unroll
            for (int np = 0; np < 2; np++) {
                uint32_t Kf[4];
                int row = kgrp * 32 + np * 16 + l7 + ((sel >> 1) << 3);
                int chunk = 2 * ks + (sel & 1);
                ldmx4(Kf, OKS + (uint32_t)(buf * 8192 + row * 128 +
                                           ((chunk ^ (row & 7)) << 4)));
                mma_bf16(S[2 * np],     Qf[ks], Kf);
                mma_bf16(S[2 * np + 1], Qf[ks], Kf + 2);
            }
        }

        // bias + P = exp2(S); write P into warp-private slice (chunks 0..3)
        {
            char* Pw = smb + 32768 + warp * 2048;
            #pragma unroll
            for (int nt = 0; nt < 4; nt++) {
                int cb = kgrp * 32 + nt * 8 + 2 * t;
                float2 k0c = *(const float2*)(kcb + cb * 2);
                float2 k1c = *(const float2*)(kcb + cb * 2 + 2);
                float dx, dy;
                dx = qc0.x - k0c.x; dy = qc0.y - k0c.y; float d00 = sqrt_approx(dx*dx + dy*dy);
                dx = qc0.x - k1c.x; dy = qc0.y - k1c.y; float d01 = sqrt_approx(dx*dx + dy*dy);
                dx = qc1.x - k0c.x; dy = qc1.y - k0c.y; float d10 = sqrt_approx(dx*dx + dy*dy);
                dx = qc1.x - k1c.x; dy = qc1.y - k1c.y; float d11 = sqrt_approx(dx*dx + dy*dy);
                uint32_t p01 = ex2bf(pkbf(fmaf(d00, we2, S[nt][0]),
                                          fmaf(d01, we2, S[nt][1])));
                uint32_t p23 = ex2bf(pkbf(fmaf(d10, we2, S[nt][2]),
                                          fmaf(d11, we2, S[nt][3])));
                uint32_t sw = (uint32_t)(((nt ^ g) << 4) + t * 4);
                *(uint32_t*)(Pw + g * 128 + sw)       = p01;
                *(uint32_t*)(Pw + (g + 8) * 128 + sw) = p23;
            }
        }
        __syncwarp();

        // O += P @ V over this group's 32 keys ; Ox += P @ ones
        #pragma unroll
        for (int kk = 0; kk < 2; kk++) {
            uint32_t Pa[4];
            {
                int row = l7 + ((sel & 1) << 3);
                int chunk = 2 * kk + (sel >> 1);
                ldmx4(Pa, OPS + (uint32_t)(warp * 2048 + row * 128 +
                                           ((chunk ^ (row & 7)) << 4)));
            }
            #pragma unroll
            for (int dp = 0; dp < 4; dp++) {
                uint32_t Vf[4];
                int row = dp * 16 + l7 + ((sel >> 1) << 3);
                int chunk = kgrp * 4 + 2 * kk + (sel & 1);
                ldmx4(Vf, OVS + (uint32_t)(buf * 8192 + row * 128 +
                                           ((chunk ^ (row & 7)) << 4)));
                mma_bf16(O[2 * dp],     Pa, Vf);
                mma_bf16(O[2 * dp + 1], Pa, Vf + 2);
            }
            mma_bf16(Ox, Pa, bones);
        }
        __syncthreads();
    }

    // exact cross-group merge through smem (reuses K/V buffers; conflict-free)
    float* mbuf = (float*)smb;
    const int slot = wq * 32 + lane;           // 0..127 within each group
    if (kgrp) {
        #pragma unroll
        for (int nt = 0; nt < 8; nt++)
            #pragma unroll
            for (int e = 0; e < 4; e++)
                mbuf[(nt * 4 + e) * 128 + slot] = O[nt][e];
        mbuf[32 * 128 + slot] = Ox[0];
        mbuf[33 * 128 + slot] = Ox[2];
    }
    __syncthreads();
    if (!kgrp) {
        #pragma unroll
        for (int nt = 0; nt < 8; nt++)
            #pragma unroll
            for (int e = 0; e < 4; e++)
                O[nt][e] += mbuf[(nt * 4 + e) * 128 + slot];
        float ox0 = Ox[0] + mbuf[32 * 128 + slot];
        float ox2 = Ox[2] + mbuf[33 * 128 + slot];
        const int src = lane & 28;
        const float l0 = __shfl_sync(0xffffffffu, ox0, src);
        const float l1 = __shfl_sync(0xffffffffu, ox2, src);
        const float i0 = 1.0f / l0, i1 = 1.0f / l1;
        #pragma unroll
        for (int nt = 0; nt < 8; nt++) {
            int col = h * 64 + nt * 8 + 2 * t;
            size_t r0 = (size_t)(b * N_TOK + n0 + wq * 16 + g) * D_MODEL + col;
            *(uint32_t*)(out + r0)               = pkhf(O[nt][0] * i0, O[nt][1] * i0);
            *(uint32_t*)(out + r0 + 8 * D_MODEL) = pkhf(O[nt][2] * i1, O[nt][3] * i1);
        }
    }
}

// ---------------- launch ---------------------------------------------------------
extern "C" void kernel_launch(void* const* d_in, const int* in_sizes, int n_in,
                              void* d_out, int out_size) {
    const float* x      = (const float*)d_in[0];
    const float* coords = (const float*)d_in[1];
    const float* ln1g = (const float*)d_in[3];
    const float* ln1b = (const float*)d_in[4];
    const float* wqkv = (const float*)d_in[5];
    const float* bqkv = (const float*)d_in[6];
    const float* wedge= (const float*)d_in[7];
    const float* wout = (const float*)d_in[8];
    const float* bout = (const float*)d_in[9];
    const float* ln2g = (const float*)d_in[10];
    const float* ln2b = (const float*)d_in[11];
    const float* w1   = (const float*)d_in[12];
    const float* b1   = (const float*)d_in[13];
    const float* w2   = (const float*)d_in[14];
    const float* b2   = (const float*)d_in[15];
    float* out = (float*)d_out;

    void *p;
    float *x2;
    __half *xln16, *att16, *hid16, *wqkv_t, *wout_t, *w1_t, *w2_t;
    __nv_bfloat16 *qp, *kp, *vtp;
    cudaGetSymbolAddress(&p, g_xln16);  xln16  = (__half*)p;
    cudaGetSymbolAddress(&p, g_qp);     qp     = (__nv_bfloat16*)p;
    cudaGetSymbolAddress(&p, g_kp);     kp     = (__nv_bfloat16*)p;
    cudaGetSymbolAddress(&p, g_vtp);    vtp    = (__nv_bfloat16*)p;
    cudaGetSymbolAddress(&p, g_att16);  att16  = (__half*)p;
    cudaGetSymbolAddress(&p, g_x2);     x2     = (float*)p;
    cudaGetSymbolAddress(&p, g_hid16);  hid16  = (__half*)p;
    cudaGetSymbolAddress(&p, g_wqkv_t); wqkv_t = (__half*)p;
    cudaGetSymbolAddress(&p, g_wout_t); wout_t = (__half*)p;
    cudaGetSymbolAddress(&p, g_w1_t);   w1_t   = (__half*)p;
    cudaGetSymbolAddress(&p, g_w2_t);   w2_t   = (__half*)p;

    const int ATTN_SMEM  = 50176;
    const int G16_SMEM_L = 2 * 128 * 128 + 2 * 8192;   // 49152
    const int G16_SMEM_S = 2 * 64 * 128 + 2 * 8192;    // 32768
    cudaFuncSetAttribute(attn_bf16, cudaFuncAttributeMaxDynamicSharedMemorySize, ATTN_SMEM);
    cudaFuncSetAttribute(gemm_qkv,  cudaFuncAttributeMaxDynamicSharedMemorySize, G16_SMEM_L);
    cudaFuncSetAttribute(gemm_f16<128,1>, cudaFuncAttributeMaxDynamicSharedMemorySize, G16_SMEM_L);
    cudaFuncSetAttribute(gemm_f16<64,0>,  cudaFuncAttributeMaxDynamicSharedMemorySize, G16_SMEM_S);

    // 0) pack + transpose weights to fp16 [N][K]
    pack_weights<<<768, 256>>>(wqkv, wout, w1, w2, wqkv_t, wout_t, w1_t, w2_t);
    // 1) LN1 (fp16 out)
    ln_kernel<<<M_ROWS, 256>>>(x, ln1g, ln1b, xln16);
    // 2) QKV fp16 GEMM + fused bf16 pack
    gemm_qkv<<<dim3(1536/64, M_ROWS/128), 128, G16_SMEM_L>>>(
        xln16, wqkv_t, bqkv, qp, kp, vtp, 1536, D_MODEL);
    // 3) attention (bf16 mma, split-KV warp groups) -> fp16 att
    attn_bf16<<<dim3(N_TOK/64, HEADS, BATCH), 256, ATTN_SMEM>>>(
        qp, kp, vtp, coords, wedge, att16);
    // 4) out proj + residual(token_embs) -> x2 fp32
    gemm_f16<64,0><<<dim3(D_MODEL/64, M_ROWS/64), 128, G16_SMEM_S>>>(
        att16, wout_t, bout, x, x2, M_ROWS, D_MODEL, D_MODEL, 0);
    // 5) LN2 (fp16 out)
    ln_kernel<<<M_ROWS, 256>>>(x2, ln2g, ln2b, xln16);
    // 6) fc1 + gelu -> hid fp16
    gemm_f16<128,1><<<dim3(HIDDEN/64, M_ROWS/128), 128, G16_SMEM_L>>>(
        xln16, w1_t, b1, nullptr, hid16, M_ROWS, HIDDEN, D_MODEL, 1);
    // 7) fc2 + residual(x2) -> out fp32
    gemm_f16<64,0><<<dim3(D_MODEL/64, M_ROWS/64), 128, G16_SMEM_S>>>(
        hid16, w2_t, b2, x2, out, M_ROWS, D_MODEL, HIDDEN, 0);
}

// round 13
// speedup vs baseline: 1.0813x; 1.0813x over previous
#include <cuda_runtime.h>
#include <cuda_bf16.h>
#include <cuda_fp16.h>
#include <math.h>
#include <stdint.h>

#define D_MODEL 512
#define N_TOK   1024
#define BATCH   2
#define HEADS   8
#define HIDDEN  2048
#define M_ROWS  (BATCH * N_TOK)   // 2048
#define LOG2E 1.4426950408889634f

// ---------------- scratch (static device globals; no allocation) ----------------
__device__ __align__(256) __half g_xln16[M_ROWS * D_MODEL];                 // LN out fp16
__device__ __align__(256) __nv_bfloat16 g_qp [M_ROWS * D_MODEL];            // Q bf16 pre-scaled
__device__ __align__(256) __nv_bfloat16 g_kp [BATCH * HEADS * N_TOK * 64];  // K [bh][key][d]
__device__ __align__(256) __nv_bfloat16 g_vtp[BATCH * HEADS * 64 * N_TOK];  // V^T [bh][d][key]
__device__ __align__(256) __half g_att16[M_ROWS * D_MODEL];                 // attn out fp16
__device__ __align__(256) float  g_x2 [M_ROWS * D_MODEL];
__device__ __align__(256) __half g_hid16[M_ROWS * HIDDEN];
// transposed fp16 weights [N][K]
__device__ __align__(256) __half g_wqkv_t[1536 * 512];
__device__ __align__(256) __half g_wout_t[512 * 512];
__device__ __align__(256) __half g_w1_t  [2048 * 512];
__device__ __align__(256) __half g_w2_t  [512 * 2048];

// ---------------- helpers --------------------------------------------------------
__device__ __forceinline__ void cp16(uint32_t smem, const void* g) {
    asm volatile("cp.async.cg.shared.global [%0], [%1], 16;" :: "r"(smem), "l"(g));
}
__device__ __forceinline__ void cp_commit() { asm volatile("cp.async.commit_group;"); }
template<int N> __device__ __forceinline__ void cp_wait() {
    asm volatile("cp.async.wait_group %0;" :: "n"(N));
}
__device__ __forceinline__ uint32_t pkbf(float a, float b) {
    __nv_bfloat162 h = __floats2bfloat162_rn(a, b);
    return *(uint32_t*)&h;
}
__device__ __forceinline__ uint32_t pkhf(float a, float b) {
    __half2 h = __floats2half2_rn(a, b);
    return *(uint32_t*)&h;
}
__device__ __forceinline__ uint32_t ex2bf(uint32_t x) {
    uint32_t r; asm("ex2.approx.ftz.bf16x2 %0, %1;" : "=r"(r) : "r"(x)); return r;
}
__device__ __forceinline__ void mma_f16(float c[4], const uint32_t a[4], const uint32_t b[2]) {
    asm volatile(
        "mma.sync.aligned.m16n8k16.row.col.f32.f16.f16.f32 "
        "{%0,%1,%2,%3}, {%4,%5,%6,%7}, {%8,%9}, {%0,%1,%2,%3};"
        : "+f"(c[0]), "+f"(c[1]), "+f"(c[2]), "+f"(c[3])
        : "r"(a[0]), "r"(a[1]), "r"(a[2]), "r"(a[3]), "r"(b[0]), "r"(b[1]));
}
__device__ __forceinline__ void mma_bf16(float c[4], const uint32_t a[4], const uint32_t b[2]) {
    asm volatile(
        "mma.sync.aligned.m16n8k16.row.col.f32.bf16.bf16.f32 "
        "{%0,%1,%2,%3}, {%4,%5,%6,%7}, {%8,%9}, {%0,%1,%2,%3};"
        : "+f"(c[0]), "+f"(c[1]), "+f"(c[2]), "+f"(c[3])
        : "r"(a[0]), "r"(a[1]), "r"(a[2]), "r"(a[3]), "r"(b[0]), "r"(b[1]));
}
__device__ __forceinline__ void ldmx4(uint32_t r[4], uint32_t addr) {
    asm volatile("ldmatrix.sync.aligned.m8n8.x4.shared.b16 {%0,%1,%2,%3}, [%4];"
                 : "=r"(r[0]), "=r"(r[1]), "=r"(r[2]), "=r"(r[3]) : "r"(addr));
}
__device__ __forceinline__ float sqrt_approx(float x) {
    float r; asm("sqrt.approx.f32 %0, %1;" : "=f"(r) : "f"(x)); return r;
}

// ---------------- weight pack: fp32 [K][N] -> fp16 [N][K] ------------------------
__global__ void pack_weights(const float* __restrict__ wqkv, const float* __restrict__ wout,
                             const float* __restrict__ w1, const float* __restrict__ w2,
                             __half* __restrict__ wqkv_t, __half* __restrict__ wout_t,
                             __half* __restrict__ w1_t, __half* __restrict__ w2_t) {
    __shared__ float tile[64][65];
    const int bx = blockIdx.x, tid = threadIdx.x;
    const float* src; __half* dst; int K, N, tk, tn;
    if (bx < 192)      { src = wqkv; dst = wqkv_t; K = 512;  N = 1536; int t = bx;       tk = t & 7;  tn = t >> 3; }
    else if (bx < 256) { src = wout; dst = wout_t; K = 512;  N = 512;  int t = bx - 192; tk = t & 7;  tn = t >> 3; }
    else if (bx < 512) { src = w1;   dst = w1_t;   K = 512;  N = 2048; int t = bx - 256; tk = t & 7;  tn = t >> 3; }
    else               { src = w2;   dst = w2_t;   K = 2048; N = 512;  int t = bx - 512; tk = t & 31; tn = t >> 5; }
    const int k0 = tk * 64, n0 = tn * 64;

    #pragma unroll
    for (int u = 0; u < 4; u++) {
        int f = tid + u * 256;
        int kr = f >> 4, nc = (f & 15) * 4;
        float4 v = *(const float4*)(src + (size_t)(k0 + kr) * N + n0 + nc);
        tile[nc + 0][kr] = v.x;
        tile[nc + 1][kr] = v.y;
        tile[nc + 2][kr] = v.z;
        tile[nc + 3][kr] = v.w;
    }
    __syncthreads();
    #pragma unroll
    for (int u = 0; u < 2; u++) {
        int f = tid + u * 256;
        int nr = f >> 3, kc = (f & 7) * 8;
        uint4 o;
        o.x = pkhf(tile[nr][kc + 0], tile[nr][kc + 1]);
        o.y = pkhf(tile[nr][kc + 2], tile[nr][kc + 3]);
        o.z = pkhf(tile[nr][kc + 4], tile[nr][kc + 5]);
        o.w = pkhf(tile[nr][kc + 6], tile[nr][kc + 7]);
        *(uint4*)(dst + (size_t)(n0 + nr) * K + k0 + kc) = o;
    }
}

// ---------------- LayerNorm (fp32 in, fp16 out) ----------------------------------
__global__ void ln_kernel(const float* __restrict__ x, const float* __restrict__ g,
                          const float* __restrict__ b, __half* __restrict__ y) {
    int row = blockIdx.x;
    const float* xr = x + (size_t)row * D_MODEL;
    int t = threadIdx.x;
    float v0 = xr[t];
    float v1 = xr[t + 256];

    __shared__ float sh[8], sh2[8];
    int w = t >> 5, lane = t & 31;

    float s = v0 + v1;
    #pragma unroll
    for (int o = 16; o; o >>= 1) s += __shfl_xor_sync(0xffffffffu, s, o);
    if (lane == 0) sh[w] = s;
    __syncthreads();
    float mean = (sh[0]+sh[1]+sh[2]+sh[3]+sh[4]+sh[5]+sh[6]+sh[7]) * (1.0f / D_MODEL);

    float d0 = v0 - mean, d1 = v1 - mean;
    float q = d0 * d0 + d1 * d1;
    #pragma unroll
    for (int o = 16; o; o >>= 1) q += __shfl_xor_sync(0xffffffffu, q, o);
    if (lane == 0) sh2[w] = q;
    __syncthreads();
    float var = (sh2[0]+sh2[1]+sh2[2]+sh2[3]+sh2[4]+sh2[5]+sh2[6]+sh2[7]) * (1.0f / D_MODEL);
    float inv = rsqrtf(var + 1e-5f);

    __half* yr = y + (size_t)row * D_MODEL;
    yr[t]       = __float2half(d0 * inv * g[t]       + b[t]);
    yr[t + 256] = __float2half(d1 * inv * g[t + 256] + b[t + 256]);
}

// ---------------- fp16 GEMM mainloop (attention-schema fragments) ----------------
#define GEMM16_BODY(A_, Bt_, K_)                                                   \
    constexpr int WM = BM / 2;                                                     \
    constexpr int MT = WM / 16;                                                    \
    extern __shared__ char smc[];                                                  \
    const uint32_t S0 = (uint32_t)__cvta_generic_to_shared(smc);                   \
    const uint32_t OAS = S0;                                                       \
    const uint32_t OBS = S0 + 2 * BM * 128;                                        \
    const int tid  = threadIdx.x;                                                  \
    const int warp = tid >> 5;                                                     \
    const int lane = tid & 31;                                                     \
    const int gpid = lane >> 2;                                                    \
    const int tgid = lane & 3;                                                     \
    const int l7   = lane & 7;                                                     \
    const int sel  = lane >> 3;                                                    \
    const int wm = warp >> 1;                                                      \
    const int wn = warp & 1;                                                       \
    const int m0 = blockIdx.y * BM;                                                \
    const int n0 = blockIdx.x * 64;                                                \
    float acc[MT][4][4];                                                           \
    _Pragma("unroll")                                                              \
    for (int i = 0; i < MT; i++)                                                   \
        _Pragma("unroll")                                                          \
        for (int j = 0; j < 4; j++)                                                \
            _Pragma("unroll")                                                      \
            for (int e = 0; e < 4; e++) acc[i][j][e] = 0.0f;                       \
    auto loadA = [&](int buf, int k0) {                                            \
        _Pragma("unroll")                                                          \
        for (int u = 0; u < BM / 16; u++) {                                        \
            int r = (tid >> 3) + u * 16; int g = tid & 7;                          \
            cp16(OAS + (uint32_t)(buf * BM * 128 + r * 128 + ((g ^ (r & 7)) << 4)),\
                 A_ + (size_t)(m0 + r) * K_ + k0 + g * 8);                         \
        }                                                                          \
    };                                                                             \
    auto loadB = [&](int buf, int k0) {                                            \
        _Pragma("unroll")                                                          \
        for (int u = 0; u < 4; u++) {                                              \
            int r = (tid >> 3) + u * 16; int g = tid & 7;                          \
            cp16(OBS + (uint32_t)(buf * 8192 + r * 128 + ((g ^ (r & 7)) << 4)),    \
                 Bt_ + (size_t)(n0 + r) * K_ + k0 + g * 8);                        \
        }                                                                          \
    };                                                                             \
    const int tiles = K_ >> 6;                                                     \
    loadA(0, 0); loadB(0, 0); cp_commit();                                         \
    for (int kt = 0; kt < tiles; kt++) {                                           \
        const int cbuf = kt & 1;                                                   \
        if (kt + 1 < tiles) {                                                      \
            loadA(cbuf ^ 1, (kt + 1) * 64);                                        \
            loadB(cbuf ^ 1, (kt + 1) * 64);                                        \
            cp_commit(); cp_wait<1>();                                             \
        } else { cp_wait<0>(); }                                                   \
        __syncthreads();                                                           \
        _Pragma("unroll")                                                          \
        for (int ks = 0; ks < 4; ks++) {                                           \
            uint32_t af[MT][4];                                                    \
            _Pragma("unroll")                                                      \
            for (int mt = 0; mt < MT; mt++) {                                      \
                int row = wm * WM + mt * 16 + l7 + ((sel & 1) << 3);               \
                int chunk = 2 * ks + (sel >> 1);                                   \
                ldmx4(af[mt], OAS + (uint32_t)(cbuf * BM * 128 + row * 128 +       \
                                               ((chunk ^ (row & 7)) << 4)));       \
            }                                                                      \
            uint32_t bf2[2][4];                                                    \
            _Pragma("unroll")                                                      \
            for (int np = 0; np < 2; np++) {                                       \
                int row = wn * 32 + np * 16 + l7 + ((sel >> 1) << 3);              \
                int chunk = 2 * ks + (sel & 1);                                    \
                ldmx4(bf2[np], OBS + (uint32_t)(cbuf * 8192 + row * 128 +          \
                                                ((chunk ^ (row & 7)) << 4)));      \
            }                                                                      \
            _Pragma("unroll")                                                      \
            for (int mt = 0; mt < MT; mt++) {                                      \
                mma_f16(acc[mt][0], af[mt], bf2[0]);                               \
                mma_f16(acc[mt][1], af[mt], bf2[0] + 2);                           \
                mma_f16(acc[mt][2], af[mt], bf2[1]);                               \
                mma_f16(acc[mt][3], af[mt], bf2[1] + 2);                           \
            }                                                                      \
        }                                                                          \
        __syncthreads();                                                           \
    }

// ---------------- generic fp16 GEMM (bias; optional gelu/residual; f32/f16 out) --
template<int BM, int OUTF16>
__global__ void __launch_bounds__(128) gemm_f16(
        const __half* __restrict__ A, const __half* __restrict__ Bt,
        const float* __restrict__ bias, const float* __restrict__ res,
        void* __restrict__ Cout, int M, int Nn, int K, int do_gelu) {
    GEMM16_BODY(A, Bt, K)

    #pragma unroll
    for (int mt = 0; mt < MT; mt++) {
        #pragma unroll
        for (int nt = 0; nt < 4; nt++) {
            int r0 = m0 + wm * WM + mt * 16 + gpid;
            int c0 = n0 + wn * 32 + nt * 8 + 2 * tgid;
            float bb0 = bias[c0], bb1 = bias[c0 + 1];
            float v00 = acc[mt][nt][0] + bb0, v01 = acc[mt][nt][1] + bb1;
            float v10 = acc[mt][nt][2] + bb0, v11 = acc[mt][nt][3] + bb1;
            if (do_gelu) {
                v00 = 0.5f * v00 * (1.0f + erff(v00 * 0.70710678118654752f));
                v01 = 0.5f * v01 * (1.0f + erff(v01 * 0.70710678118654752f));
                v10 = 0.5f * v10 * (1.0f + erff(v10 * 0.70710678118654752f));
                v11 = 0.5f * v11 * (1.0f + erff(v11 * 0.70710678118654752f));
            }
            if (res) {
                v00 += res[(size_t)r0 * Nn + c0];
                v01 += res[(size_t)r0 * Nn + c0 + 1];
                v10 += res[(size_t)(r0 + 8) * Nn + c0];
                v11 += res[(size_t)(r0 + 8) * Nn + c0 + 1];
            }
            if (OUTF16) {
                __half* C = (__half*)Cout;
                *(uint32_t*)(C + (size_t)r0 * Nn + c0)       = pkhf(v00, v01);
                *(uint32_t*)(C + (size_t)(r0 + 8) * Nn + c0) = pkhf(v10, v11);
            } else {
                float* C = (float*)Cout;
                *(float2*)(C + (size_t)r0 * Nn + c0)       = make_float2(v00, v01);
                *(float2*)(C + (size_t)(r0 + 8) * Nn + c0) = make_float2(v10, v11);
            }
        }
    }
}

// ---------------- QKV fp16 GEMM with fused bf16 pack epilogue --------------------
__global__ void __launch_bounds__(128) gemm_qkv(
        const __half* __restrict__ A, const __half* __restrict__ Bt,
        const float* __restrict__ bias,
        __nv_bfloat16* __restrict__ qp, __nv_bfloat16* __restrict__ kp,
        __nv_bfloat16* __restrict__ vtp, int Nn, int K) {
    constexpr int BM = 128;
    GEMM16_BODY(A, Bt, K)

    const int region = n0 / 512;
    const int h = (n0 % 512) / 64;
    #pragma unroll
    for (int mt = 0; mt < MT; mt++) {
        #pragma unroll
        for (int nt = 0; nt < 4; nt++) {
            int r0 = m0 + wm * WM + mt * 16 + gpid;
            int lc = wn * 32 + nt * 8 + 2 * tgid;
            int c0 = n0 + lc;
            float bb0 = bias[c0], bb1 = bias[c0 + 1];
            float v00 = acc[mt][nt][0] + bb0, v01 = acc[mt][nt][1] + bb1;
            float v10 = acc[mt][nt][2] + bb0, v11 = acc[mt][nt][3] + bb1;
            int bb_ = r0 >> 10, key = r0 & 1023;
            int bh  = bb_ * HEADS + h;
            if (region == 0) {
                const float qs = 0.125f * LOG2E;
                size_t a0 = (size_t)(bb_ * N_TOK + key) * D_MODEL + h * 64 + lc;
                *(uint32_t*)(qp + a0)                 = pkbf(v00 * qs, v01 * qs);
                *(uint32_t*)(qp + a0 + 8 * D_MODEL)   = pkbf(v10 * qs, v11 * qs);
            } else if (region == 1) {
                size_t a0 = (size_t)(bh * N_TOK + key) * 64 + lc;
                *(uint32_t*)(kp + a0)        = pkbf(v00, v01);
                *(uint32_t*)(kp + a0 + 512)  = pkbf(v10, v11);
            } else {
                size_t a0 = (size_t)(bh * 64 + lc) * N_TOK + key;
                vtp[a0]              = __float2bfloat16(v00);
                vtp[a0 + N_TOK]      = __float2bfloat16(v01);
                vtp[a0 + 8]          = __float2bfloat16(v10);
                vtp[a0 + N_TOK + 8]  = __float2bfloat16(v11);
            }
        }
    }
}

// ---------------- bf16 mma flash attention, split-KV, register-P -----------------
// 256 threads = 8 warps; warps 0-3 keys [0,32) per tile, warps 4-7 keys [32,64).
// P never touches smem: the packed exp2 outputs (p01 at row g cols 2t..2t+1,
// p23 at row g+8) ARE the mma A-fragment registers for P@V (FA2 layout identity):
//   A k-chunk kk: {p01[2kk], p23[2kk], p01[2kk+1], p23[2kk+1]}.
// No-max exp2 softmax -> cross-group merge is an exact sum via smem, once.
// smem: Ks[2][8KB]@0, Vs[2][8KB]@16384, Qstage 8KB@32768, kc[2][512B]@40960 => 41984 B
__global__ void __launch_bounds__(256) attn_bf16(
        const __nv_bfloat16* __restrict__ qp, const __nv_bfloat16* __restrict__ kp,
        const __nv_bfloat16* __restrict__ vtp, const float* __restrict__ coords,
        const float* __restrict__ w_edge, __half* __restrict__ out) {
    extern __shared__ char smb[];
    const uint32_t S0 = (uint32_t)__cvta_generic_to_shared(smb);
    const uint32_t OKS = S0, OVS = S0 + 16384, OPS = S0 + 32768;
    const uint32_t OKC = S0 + 40960;

    const int b = blockIdx.z, h = blockIdx.y, n0 = blockIdx.x * 64;
    const int bh = b * HEADS + h;
    const int tid = threadIdx.x, warp = tid >> 5, lane = tid & 31;
    const int kgrp = warp >> 2, wq = warp & 3;
    const int g = lane >> 2, t = lane & 3;
    const int l7 = lane & 7, sel = lane >> 3;
    const float we2 = w_edge[2 * HEADS + h] * LOG2E;

    const uint32_t bone = (lane < 4) ? 0x3F803F80u : 0u;
    const uint32_t bones[2] = {bone, bone};

    auto issue = [&](int buf, int m0) {
        #pragma unroll
        for (int u = 0; u < 2; u++) {
            int f = tid + u * 256; int r = f >> 3; int c = f & 7;
            uint32_t off = (uint32_t)(buf * 8192 + r * 128 + ((c ^ (r & 7)) << 4));
            cp16(OKS + off, kp  + (size_t)(bh * N_TOK + m0 + r) * 64 + c * 8);
            cp16(OVS + off, vtp + (size_t)(bh * 64 + r) * N_TOK + m0 + c * 8);
        }
        if (tid < 32)
            cp16(OKC + (uint32_t)(buf * 512 + tid * 16),
                 coords + (size_t)(b * N_TOK + m0) * 2 + tid * 4);
    };

    issue(0, 0);
    #pragma unroll
    for (int u = 0; u < 2; u++) {
        int f = tid + u * 256; int r = f >> 3; int c = f & 7;
        cp16(OPS + (uint32_t)(r * 128 + ((c ^ (r & 7)) << 4)),
             qp + (size_t)(b * N_TOK + n0 + r) * D_MODEL + h * 64 + c * 8);
    }
    cp_commit();

    const int qr0 = n0 + wq * 16 + g;
    float2 qc0 = *(const float2*)(coords + (size_t)(b * N_TOK + qr0) * 2);
    float2 qc1 = *(const float2*)(coords + (size_t)(b * N_TOK + qr0 + 8) * 2);

    cp_wait<0>();
    __syncthreads();

    uint32_t Qf[4][4];
    {
        const int row = wq * 16 + l7 + ((sel & 1) << 3);
        #pragma unroll
        for (int ks = 0; ks < 4; ks++) {
            int chunk = 2 * ks + (sel >> 1);
            ldmx4(Qf[ks], OPS + (uint32_t)(row * 128 + ((chunk ^ (row & 7)) << 4)));
        }
    }

    float O[8][4];
    #pragma unroll
    for (int nt = 0; nt < 8; nt++)
        #pragma unroll
        for (int e = 0; e < 4; e++) O[nt][e] = 0.0f;
    float Ox[4] = {0.0f, 0.0f, 0.0f, 0.0f};

    for (int it = 0; it < 16; it++) {
        const int buf = it & 1;
        if (it + 1 < 16) { issue(buf ^ 1, (it + 1) * 64); cp_commit(); cp_wait<1>(); }
        else cp_wait<0>();
        __syncthreads();

        const float* kcb = (const float*)(smb + 40960 + buf * 512);

        // S = Q @ K^T over this group's 32 keys
        float S[4][4];
        #pragma unroll
        for (int nt = 0; nt < 4; nt++)
            #pragma unroll
            for (int e = 0; e < 4; e++) S[nt][e] = 0.0f;
        #pragma unroll
        for (int ks = 0; ks < 4; ks++) {
            #pragma unroll
            for (int np = 0; np < 2; np++) {
                uint32_t Kf[4];
                int row = kgrp * 32 + np * 16 + l7 + ((sel >> 1) << 3);
                int chunk = 2 * ks + (sel & 1);
                ldmx4(Kf, OKS + (uint32_t)(buf * 8192 + row * 128 +
                                           ((chunk ^ (row & 7)) << 4)));
                mma_bf16(S[2 * np],     Qf[ks], Kf);
                mma_bf16(S[2 * np + 1], Qf[ks], Kf + 2);
            }
        }

        // bias + P = exp2(S), packed bf16x2 pairs stay in registers (A-frag layout)
        uint32_t Pp[4][2];
        #pragma unroll
        for (int nt = 0; nt < 4; nt++) {
            int cb = kgrp * 32 + nt * 8 + 2 * t;
            float2 k0c = *(const float2*)(kcb + cb * 2);
            float2 k1c = *(const float2*)(kcb + cb * 2 + 2);
            float dx, dy;
            dx = qc0.x - k0c.x; dy = qc0.y - k0c.y; float d00 = sqrt_approx(dx*dx + dy*dy);
            dx = qc0.x - k1c.x; dy = qc0.y - k1c.y; float d01 = sqrt_approx(dx*dx + dy*dy);
            dx = qc1.x - k0c.x; dy = qc1.y - k0c.y; float d10 = sqrt_approx(dx*dx + dy*dy);
            dx = qc1.x - k1c.x; dy = qc1.y - k1c.y; float d11 = sqrt_approx(dx*dx + dy*dy);
            Pp[nt][0] = ex2bf(pkbf(fmaf(d00, we2, S[nt][0]),
                                   fmaf(d01, we2, S[nt][1])));
            Pp[nt][1] = ex2bf(pkbf(fmaf(d10, we2, S[nt][2]),
                                   fmaf(d11, we2, S[nt][3])));
        }

        // O += P @ V ; Ox += P @ ones — P directly from registers
        #pragma unroll
        for (int kk = 0; kk < 2; kk++) {
            uint32_t Pa[4] = {Pp[2 * kk][0], Pp[2 * kk][1],
                              Pp[2 * kk + 1][0], Pp[2 * kk + 1][1]};
            #pragma unroll
            for (int dp = 0; dp < 4; dp++) {
                uint32_t Vf[4];
                int row = dp * 16 + l7 + ((sel >> 1) << 3);
                int chunk = kgrp * 4 + 2 * kk + (sel & 1);
                ldmx4(Vf, OVS + (uint32_t)(buf * 8192 + row * 128 +
                                           ((chunk ^ (row & 7)) << 4)));
                mma_bf16(O[2 * dp],     Pa, Vf);
                mma_bf16(O[2 * dp + 1], Pa, Vf + 2);
            }
            mma_bf16(Ox, Pa, bones);
        }
        __syncthreads();
    }

    // exact cross-group merge through smem (reuses K/V buffers; conflict-free)
    float* mbuf = (float*)smb;
    const int slot = wq * 32 + lane;           // 0..127 within each group
    if (kgrp) {
        #pragma unroll
        for (int nt = 0; nt < 8; nt++)
            #pragma unroll
            for (int e = 0; e < 4; e++)
                mbuf[(nt * 4 + e) * 128 + slot] = O[nt][e];
        mbuf[32 * 128 + slot] = Ox[0];
        mbuf[33 * 128 + slot] = Ox[2];
    }
    __syncthreads();
    if (!kgrp) {
        #pragma unroll
        for (int nt = 0; nt < 8; nt++)
            #pragma unroll
            for (int e = 0; e < 4; e++)
                O[nt][e] += mbuf[(nt * 4 + e) * 128 + slot];
        float ox0 = Ox[0] + mbuf[32 * 128 + slot];
        float ox2 = Ox[2] + mbuf[33 * 128 + slot];
        const int src = lane & 28;
        const float l0 = __shfl_sync(0xffffffffu, ox0, src);
        const float l1 = __shfl_sync(0xffffffffu, ox2, src);
        const float i0 = 1.0f / l0, i1 = 1.0f / l1;
        #pragma unroll
        for (int nt = 0; nt < 8; nt++) {
            int col = h * 64 + nt * 8 + 2 * t;
            size_t r0 = (size_t)(b * N_TOK + n0 + wq * 16 + g) * D_MODEL + col;
            *(uint32_t*)(out + r0)               = pkhf(O[nt][0] * i0, O[nt][1] * i0);
            *(uint32_t*)(out + r0 + 8 * D_MODEL) = pkhf(O[nt][2] * i1, O[nt][3] * i1);
        }
    }
}

// ---------------- launch ---------------------------------------------------------
extern "C" void kernel_launch(void* const* d_in, const int* in_sizes, int n_in,
                              void* d_out, int out_size) {
    const float* x      = (const float*)d_in[0];
    const float* coords = (const float*)d_in[1];
    const float* ln1g = (const float*)d_in[3];
    const float* ln1b = (const float*)d_in[4];
    const float* wqkv = (const float*)d_in[5];
    const float* bqkv = (const float*)d_in[6];
    const float* wedge= (const float*)d_in[7];
    const float* wout = (const float*)d_in[8];
    const float* bout = (const float*)d_in[9];
    const float* ln2g = (const float*)d_in[10];
    const float* ln2b = (const float*)d_in[11];
    const float* w1   = (const float*)d_in[12];
    const float* b1   = (const float*)d_in[13];
    const float* w2   = (const float*)d_in[14];
    const float* b2   = (const float*)d_in[15];
    float* out = (float*)d_out;

    void *p;
    float *x2;
    __half *xln16, *att16, *hid16, *wqkv_t, *wout_t, *w1_t, *w2_t;
    __nv_bfloat16 *qp, *kp, *vtp;
    cudaGetSymbolAddress(&p, g_xln16);  xln16  = (__half*)p;
    cudaGetSymbolAddress(&p, g_qp);     qp     = (__nv_bfloat16*)p;
    cudaGetSymbolAddress(&p, g_kp);     kp     = (__nv_bfloat16*)p;
    cudaGetSymbolAddress(&p, g_vtp);    vtp    = (__nv_bfloat16*)p;
    cudaGetSymbolAddress(&p, g_att16);  att16  = (__half*)p;
    cudaGetSymbolAddress(&p, g_x2);     x2     = (float*)p;
    cudaGetSymbolAddress(&p, g_hid16);  hid16  = (__half*)p;
    cudaGetSymbolAddress(&p, g_wqkv_t); wqkv_t = (__half*)p;
    cudaGetSymbolAddress(&p, g_wout_t); wout_t = (__half*)p;
    cudaGetSymbolAddress(&p, g_w1_t);   w1_t   = (__half*)p;
    cudaGetSymbolAddress(&p, g_w2_t);   w2_t   = (__half*)p;

    const int ATTN_SMEM  = 41984;
    const int G16_SMEM_L = 2 * 128 * 128 + 2 * 8192;   // 49152
    const int G16_SMEM_S = 2 * 64 * 128 + 2 * 8192;    // 32768
    cudaFuncSetAttribute(attn_bf16, cudaFuncAttributeMaxDynamicSharedMemorySize, ATTN_SMEM);
    cudaFuncSetAttribute(gemm_qkv,  cudaFuncAttributeMaxDynamicSharedMemorySize, G16_SMEM_L);
    cudaFuncSetAttribute(gemm_f16<128,1>, cudaFuncAttributeMaxDynamicSharedMemorySize, G16_SMEM_L);
    cudaFuncSetAttribute(gemm_f16<64,0>,  cudaFuncAttributeMaxDynamicSharedMemorySize, G16_SMEM_S);

    // 0) pack + transpose weights to fp16 [N][K]
    pack_weights<<<768, 256>>>(wqkv, wout, w1, w2, wqkv_t, wout_t, w1_t, w2_t);
    // 1) LN1 (fp16 out)
    ln_kernel<<<M_ROWS, 256>>>(x, ln1g, ln1b, xln16);
    // 2) QKV fp16 GEMM + fused bf16 pack
    gemm_qkv<<<dim3(1536/64, M_ROWS/128), 128, G16_SMEM_L>>>(
        xln16, wqkv_t, bqkv, qp, kp, vtp, 1536, D_MODEL);
    // 3) attention (bf16 mma, split-KV, register-P) -> fp16 att
    attn_bf16<<<dim3(N_TOK/64, HEADS, BATCH), 256, ATTN_SMEM>>>(
        qp, kp, vtp, coords, wedge, att16);
    // 4) out proj + residual(token_embs) -> x2 fp32
    gemm_f16<64,0><<<dim3(D_MODEL/64, M_ROWS/64), 128, G16_SMEM_S>>>(
        att16, wout_t, bout, x, x2, M_ROWS, D_MODEL, D_MODEL, 0);
    // 5) LN2 (fp16 out)
    ln_kernel<<<M_ROWS, 256>>>(x2, ln2g, ln2b, xln16);
    // 6) fc1 + gelu -> hid fp16
    gemm_f16<128,1><<<dim3(HIDDEN/64, M_ROWS/128), 128, G16_SMEM_L>>>(
        xln16, w1_t, b1, nullptr, hid16, M_ROWS, HIDDEN, D_MODEL, 1);
    // 7) fc2 + residual(x2) -> out fp32
    gemm_f16<64,0><<<dim3(D_MODEL/64, M_ROWS/64), 128, G16_SMEM_S>>>(
        hid16, w2_t, b2, x2, out, M_ROWS, D_MODEL, HIDDEN, 0);
}

// round 14
// speedup vs baseline: 1.1042x; 1.0212x over previous
#include <cuda_runtime.h>
#include <cuda_bf16.h>
#include <cuda_fp16.h>
#include <math.h>
#include <stdint.h>

#define D_MODEL 512
#define N_TOK   1024
#define BATCH   2
#define HEADS   8
#define HIDDEN  2048
#define M_ROWS  (BATCH * N_TOK)   // 2048
#define LOG2E 1.4426950408889634f

// ---------------- scratch (static device globals; no allocation) ----------------
__device__ __align__(256) __half g_xln16[M_ROWS * D_MODEL];                 // LN out fp16
__device__ __align__(256) __nv_bfloat16 g_qp [M_ROWS * D_MODEL];            // Q bf16 pre-scaled
__device__ __align__(256) __nv_bfloat16 g_kp [BATCH * HEADS * N_TOK * 64];  // K [bh][key][d]
__device__ __align__(256) __nv_bfloat16 g_vtp[BATCH * HEADS * 64 * N_TOK];  // V^T [bh][d][key]
__device__ __align__(256) __nv_bfloat16 g_db [BATCH * N_TOK * N_TOK];       // dist bf16 (4MB, L2)
__device__ __align__(256) __half g_att16[M_ROWS * D_MODEL];                 // attn out fp16
__device__ __align__(256) float  g_x2 [M_ROWS * D_MODEL];
__device__ __align__(256) __half g_hid16[M_ROWS * HIDDEN];
// transposed fp16 weights [N][K]
__device__ __align__(256) __half g_wqkv_t[1536 * 512];
__device__ __align__(256) __half g_wout_t[512 * 512];
__device__ __align__(256) __half g_w1_t  [2048 * 512];
__device__ __align__(256) __half g_w2_t  [512 * 2048];

// ---------------- helpers --------------------------------------------------------
__device__ __forceinline__ void cp16(uint32_t smem, const void* g) {
    asm volatile("cp.async.cg.shared.global [%0], [%1], 16;" :: "r"(smem), "l"(g));
}
__device__ __forceinline__ void cp_commit() { asm volatile("cp.async.commit_group;"); }
template<int N> __device__ __forceinline__ void cp_wait() {
    asm volatile("cp.async.wait_group %0;" :: "n"(N));
}
__device__ __forceinline__ uint32_t pkbf(float a, float b) {
    __nv_bfloat162 h = __floats2bfloat162_rn(a, b);
    return *(uint32_t*)&h;
}
__device__ __forceinline__ uint32_t pkhf(float a, float b) {
    __half2 h = __floats2half2_rn(a, b);
    return *(uint32_t*)&h;
}
__device__ __forceinline__ uint32_t ex2bf(uint32_t x) {
    uint32_t r; asm("ex2.approx.ftz.bf16x2 %0, %1;" : "=r"(r) : "r"(x)); return r;
}
__device__ __forceinline__ void mma_f16(float c[4], const uint32_t a[4], const uint32_t b[2]) {
    asm volatile(
        "mma.sync.aligned.m16n8k16.row.col.f32.f16.f16.f32 "
        "{%0,%1,%2,%3}, {%4,%5,%6,%7}, {%8,%9}, {%0,%1,%2,%3};"
        : "+f"(c[0]), "+f"(c[1]), "+f"(c[2]), "+f"(c[3])
        : "r"(a[0]), "r"(a[1]), "r"(a[2]), "r"(a[3]), "r"(b[0]), "r"(b[1]));
}
__device__ __forceinline__ void mma_bf16(float c[4], const uint32_t a[4], const uint32_t b[2]) {
    asm volatile(
        "mma.sync.aligned.m16n8k16.row.col.f32.bf16.bf16.f32 "
        "{%0,%1,%2,%3}, {%4,%5,%6,%7}, {%8,%9}, {%0,%1,%2,%3};"
        : "+f"(c[0]), "+f"(c[1]), "+f"(c[2]), "+f"(c[3])
        : "r"(a[0]), "r"(a[1]), "r"(a[2]), "r"(a[3]), "r"(b[0]), "r"(b[1]));
}
__device__ __forceinline__ void ldmx4(uint32_t r[4], uint32_t addr) {
    asm volatile("ldmatrix.sync.aligned.m8n8.x4.shared.b16 {%0,%1,%2,%3}, [%4];"
                 : "=r"(r[0]), "=r"(r[1]), "=r"(r[2]), "=r"(r[3]) : "r"(addr));
}
__device__ __forceinline__ float sqrt_approx(float x) {
    float r; asm("sqrt.approx.f32 %0, %1;" : "=f"(r) : "f"(x)); return r;
}

// ---------------- prep: weight pack + LN1 + pairwise dist (one launch) -----------
// blocks [0,768): weight transpose->fp16; [768,2816): LN1 rows; [2816,4864): dist rows
__global__ void prep_kernel(
        const float* __restrict__ wqkv, const float* __restrict__ wout,
        const float* __restrict__ w1, const float* __restrict__ w2,
        __half* __restrict__ wqkv_t, __half* __restrict__ wout_t,
        __half* __restrict__ w1_t, __half* __restrict__ w2_t,
        const float* __restrict__ x, const float* __restrict__ g1,
        const float* __restrict__ b1, __half* __restrict__ xln16,
        const float* __restrict__ coords, __nv_bfloat16* __restrict__ db) {
    const int bx = blockIdx.x, tid = threadIdx.x;

    if (bx < 768) {               // ---- weight pack ----
        __shared__ float tile[64][65];
        const float* src; __half* dst; int K, N, tk, tn;
        if (bx < 192)      { src = wqkv; dst = wqkv_t; K = 512;  N = 1536; int t = bx;       tk = t & 7;  tn = t >> 3; }
        else if (bx < 256) { src = wout; dst = wout_t; K = 512;  N = 512;  int t = bx - 192; tk = t & 7;  tn = t >> 3; }
        else if (bx < 512) { src = w1;   dst = w1_t;   K = 512;  N = 2048; int t = bx - 256; tk = t & 7;  tn = t >> 3; }
        else               { src = w2;   dst = w2_t;   K = 2048; N = 512;  int t = bx - 512; tk = t & 31; tn = t >> 5; }
        const int k0 = tk * 64, n0 = tn * 64;

        #pragma unroll
        for (int u = 0; u < 4; u++) {
            int f = tid + u * 256;
            int kr = f >> 4, nc = (f & 15) * 4;
            float4 v = *(const float4*)(src + (size_t)(k0 + kr) * N + n0 + nc);
            tile[nc + 0][kr] = v.x;
            tile[nc + 1][kr] = v.y;
            tile[nc + 2][kr] = v.z;
            tile[nc + 3][kr] = v.w;
        }
        __syncthreads();
        #pragma unroll
        for (int u = 0; u < 2; u++) {
            int f = tid + u * 256;
            int nr = f >> 3, kc = (f & 7) * 8;
            uint4 o;
            o.x = pkhf(tile[nr][kc + 0], tile[nr][kc + 1]);
            o.y = pkhf(tile[nr][kc + 2], tile[nr][kc + 3]);
            o.z = pkhf(tile[nr][kc + 4], tile[nr][kc + 5]);
            o.w = pkhf(tile[nr][kc + 6], tile[nr][kc + 7]);
            *(uint4*)(dst + (size_t)(n0 + nr) * K + k0 + kc) = o;
        }
    } else if (bx < 2816) {       // ---- LN1 ----
        __shared__ float sh[8], sh2[8];
        const int row = bx - 768;
        const float* xr = x + (size_t)row * D_MODEL;
        float v0 = xr[tid], v1 = xr[tid + 256];
        int w = tid >> 5, lane = tid & 31;

        float s = v0 + v1;
        #pragma unroll
        for (int o = 16; o; o >>= 1) s += __shfl_xor_sync(0xffffffffu, s, o);
        if (lane == 0) sh[w] = s;
        __syncthreads();
        float mean = (sh[0]+sh[1]+sh[2]+sh[3]+sh[4]+sh[5]+sh[6]+sh[7]) * (1.0f / D_MODEL);

        float d0 = v0 - mean, d1 = v1 - mean;
        float q = d0 * d0 + d1 * d1;
        #pragma unroll
        for (int o = 16; o; o >>= 1) q += __shfl_xor_sync(0xffffffffu, q, o);
        if (lane == 0) sh2[w] = q;
        __syncthreads();
        float var = (sh2[0]+sh2[1]+sh2[2]+sh2[3]+sh2[4]+sh2[5]+sh2[6]+sh2[7]) * (1.0f / D_MODEL);
        float inv = rsqrtf(var + 1e-5f);

        __half* yr = xln16 + (size_t)row * D_MODEL;
        yr[tid]       = __float2half(d0 * inv * g1[tid]       + b1[tid]);
        yr[tid + 256] = __float2half(d1 * inv * g1[tid + 256] + b1[tid + 256]);
    } else {                      // ---- pairwise distances (bf16) ----
        const int idx = bx - 2816;
        const int b = idx >> 10, n = idx & 1023;
        float2 q = ((const float2*)coords)[b * N_TOK + n];
        const int m0 = tid * 4;
        const float4* cp4 = (const float4*)(coords + (size_t)b * N_TOK * 2);
        float4 ca = cp4[m0 >> 1];
        float4 cb = cp4[(m0 >> 1) + 1];
        float dx, dy, d0, d1, d2, d3;
        dx = q.x - ca.x; dy = q.y - ca.y; d0 = sqrt_approx(dx*dx + dy*dy);
        dx = q.x - ca.z; dy = q.y - ca.w; d1 = sqrt_approx(dx*dx + dy*dy);
        dx = q.x - cb.x; dy = q.y - cb.y; d2 = sqrt_approx(dx*dx + dy*dy);
        dx = q.x - cb.z; dy = q.y - cb.w; d3 = sqrt_approx(dx*dx + dy*dy);
        uint2 o;
        o.x = pkbf(d0, d1);
        o.y = pkbf(d2, d3);
        *(uint2*)(db + (size_t)(b * N_TOK + n) * N_TOK + m0) = o;
    }
}

// ---------------- LayerNorm (fp32 in, fp16 out) ----------------------------------
__global__ void ln_kernel(const float* __restrict__ x, const float* __restrict__ g,
                          const float* __restrict__ b, __half* __restrict__ y) {
    int row = blockIdx.x;
    const float* xr = x + (size_t)row * D_MODEL;
    int t = threadIdx.x;
    float v0 = xr[t];
    float v1 = xr[t + 256];

    __shared__ float sh[8], sh2[8];
    int w = t >> 5, lane = t & 31;

    float s = v0 + v1;
    #pragma unroll
    for (int o = 16; o; o >>= 1) s += __shfl_xor_sync(0xffffffffu, s, o);
    if (lane == 0) sh[w] = s;
    __syncthreads();
    float mean = (sh[0]+sh[1]+sh[2]+sh[3]+sh[4]+sh[5]+sh[6]+sh[7]) * (1.0f / D_MODEL);

    float d0 = v0 - mean, d1 = v1 - mean;
    float q = d0 * d0 + d1 * d1;
    #pragma unroll
    for (int o = 16; o; o >>= 1) q += __shfl_xor_sync(0xffffffffu, q, o);
    if (lane == 0) sh2[w] = q;
    __syncthreads();
    float var = (sh2[0]+sh2[1]+sh2[2]+sh2[3]+sh2[4]+sh2[5]+sh2[6]+sh2[7]) * (1.0f / D_MODEL);
    float inv = rsqrtf(var + 1e-5f);

    __half* yr = y + (size_t)row * D_MODEL;
    yr[t]       = __float2half(d0 * inv * g[t]       + b[t]);
    yr[t + 256] = __float2half(d1 * inv * g[t + 256] + b[t + 256]);
}

// ---------------- fp16 GEMM mainloop (attention-schema fragments) ----------------
#define GEMM16_BODY(A_, Bt_, K_)                                                   \
    constexpr int WM = BM / 2;                                                     \
    constexpr int MT = WM / 16;                                                    \
    extern __shared__ char smc[];                                                  \
    const uint32_t S0 = (uint32_t)__cvta_generic_to_shared(smc);                   \
    const uint32_t OAS = S0;                                                       \
    const uint32_t OBS = S0 + 2 * BM * 128;                                        \
    const int tid  = threadIdx.x;                                                  \
    const int warp = tid >> 5;                                                     \
    const int lane = tid & 31;                                                     \
    const int gpid = lane >> 2;                                                    \
    const int tgid = lane & 3;                                                     \
    const int l7   = lane & 7;                                                     \
    const int sel  = lane >> 3;                                                    \
    const int wm = warp >> 1;                                                      \
    const int wn = warp & 1;                                                       \
    const int m0 = blockIdx.y * BM;                                                \
    const int n0 = blockIdx.x * 64;                                                \
    float acc[MT][4][4];                                                           \
    _Pragma("unroll")                                                              \
    for (int i = 0; i < MT; i++)                                                   \
        _Pragma("unroll")                                                          \
        for (int j = 0; j < 4; j++)                                                \
            _Pragma("unroll")                                                      \
            for (int e = 0; e < 4; e++) acc[i][j][e] = 0.0f;                       \
    auto loadA = [&](int buf, int k0) {                                            \
        _Pragma("unroll")                                                          \
        for (int u = 0; u < BM / 16; u++) {                                        \
            int r = (tid >> 3) + u * 16; int g = tid & 7;                          \
            cp16(OAS + (uint32_t)(buf * BM * 128 + r * 128 + ((g ^ (r & 7)) << 4)),\
                 A_ + (size_t)(m0 + r) * K_ + k0 + g * 8);                         \
        }                                                                          \
    };                                                                             \
    auto loadB = [&](int buf, int k0) {                                            \
        _Pragma("unroll")                                                          \
        for (int u = 0; u < 4; u++) {                                              \
            int r = (tid >> 3) + u * 16; int g = tid & 7;                          \
            cp16(OBS + (uint32_t)(buf * 8192 + r * 128 + ((g ^ (r & 7)) << 4)),    \
                 Bt_ + (size_t)(n0 + r) * K_ + k0 + g * 8);                        \
        }                                                                          \
    };                                                                             \
    const int tiles = K_ >> 6;                                                     \
    loadA(0, 0); loadB(0, 0); cp_commit();                                         \
    for (int kt = 0; kt < tiles; kt++) {                                           \
        const int cbuf = kt & 1;                                                   \
        if (kt + 1 < tiles) {                                                      \
            loadA(cbuf ^ 1, (kt + 1) * 64);                                        \
            loadB(cbuf ^ 1, (kt + 1) * 64);                                        \
            cp_commit(); cp_wait<1>();                                             \
        } else { cp_wait<0>(); }                                                   \
        __syncthreads();                                                           \
        _Pragma("unroll")                                                          \
        for (int ks = 0; ks < 4; ks++) {                                           \
            uint32_t af[MT][4];                                                    \
            _Pragma("unroll")                                                      \
            for (int mt = 0; mt < MT; mt++) {                                      \
                int row = wm * WM + mt * 16 + l7 + ((sel & 1) << 3);               \
                int chunk = 2 * ks + (sel >> 1);                                   \
                ldmx4(af[mt], OAS + (uint32_t)(cbuf * BM * 128 + row * 128 +       \
                                               ((chunk ^ (row & 7)) << 4)));       \
            }                                                                      \
            uint32_t bf2[2][4];                                                    \
            _Pragma("unroll")                                                      \
            for (int np = 0; np < 2; np++) {                                       \
                int row = wn * 32 + np * 16 + l7 + ((sel >> 1) << 3);              \
                int chunk = 2 * ks + (sel & 1);                                    \
                ldmx4(bf2[np], OBS + (uint32_t)(cbuf * 8192 + row * 128 +          \
                                                ((chunk ^ (row & 7)) << 4)));      \
            }                                                                      \
            _Pragma("unroll")                                                      \
            for (int mt = 0; mt < MT; mt++) {                                      \
                mma_f16(acc[mt][0], af[mt], bf2[0]);                               \
                mma_f16(acc[mt][1], af[mt], bf2[0] + 2);                           \
                mma_f16(acc[mt][2], af[mt], bf2[1]);                               \
                mma_f16(acc[mt][3], af[mt], bf2[1] + 2);                           \
            }                                                                      \
        }                                                                          \
        __syncthreads();                                                           \
    }

// ---------------- generic fp16 GEMM (bias; optional gelu/residual; f32/f16 out) --
template<int BM, int OUTF16>
__global__ void __launch_bounds__(128) gemm_f16(
        const __half* __restrict__ A, const __half* __restrict__ Bt,
        const float* __restrict__ bias, const float* __restrict__ res,
        void* __restrict__ Cout, int M, int Nn, int K, int do_gelu) {
    GEMM16_BODY(A, Bt, K)

    #pragma unroll
    for (int mt = 0; mt < MT; mt++) {
        #pragma unroll
        for (int nt = 0; nt < 4; nt++) {
            int r0 = m0 + wm * WM + mt * 16 + gpid;
            int c0 = n0 + wn * 32 + nt * 8 + 2 * tgid;
            float bb0 = bias[c0], bb1 = bias[c0 + 1];
            float v00 = acc[mt][nt][0] + bb0, v01 = acc[mt][nt][1] + bb1;
            float v10 = acc[mt][nt][2] + bb0, v11 = acc[mt][nt][3] + bb1;
            if (do_gelu) {
                v00 = 0.5f * v00 * (1.0f + erff(v00 * 0.70710678118654752f));
                v01 = 0.5f * v01 * (1.0f + erff(v01 * 0.70710678118654752f));
                v10 = 0.5f * v10 * (1.0f + erff(v10 * 0.70710678118654752f));
                v11 = 0.5f * v11 * (1.0f + erff(v11 * 0.70710678118654752f));
            }
            if (res) {
                v00 += res[(size_t)r0 * Nn + c0];
                v01 += res[(size_t)r0 * Nn + c0 + 1];
                v10 += res[(size_t)(r0 + 8) * Nn + c0];
                v11 += res[(size_t)(r0 + 8) * Nn + c0 + 1];
            }
            if (OUTF16) {
                __half* C = (__half*)Cout;
                *(uint32_t*)(C + (size_t)r0 * Nn + c0)       = pkhf(v00, v01);
                *(uint32_t*)(C + (size_t)(r0 + 8) * Nn + c0) = pkhf(v10, v11);
            } else {
                float* C = (float*)Cout;
                *(float2*)(C + (size_t)r0 * Nn + c0)       = make_float2(v00, v01);
                *(float2*)(C + (size_t)(r0 + 8) * Nn + c0) = make_float2(v10, v11);
            }
        }
    }
}

// ---------------- QKV fp16 GEMM with fused bf16 pack epilogue --------------------
__global__ void __launch_bounds__(128) gemm_qkv(
        const __half* __restrict__ A, const __half* __restrict__ Bt,
        const float* __restrict__ bias,
        __nv_bfloat16* __restrict__ qp, __nv_bfloat16* __restrict__ kp,
        __nv_bfloat16* __restrict__ vtp, int Nn, int K) {
    constexpr int BM = 128;
    GEMM16_BODY(A, Bt, K)

    const int region = n0 / 512;
    const int h = (n0 % 512) / 64;
    #pragma unroll
    for (int mt = 0; mt < MT; mt++) {
        #pragma unroll
        for (int nt = 0; nt < 4; nt++) {
            int r0 = m0 + wm * WM + mt * 16 + gpid;
            int lc = wn * 32 + nt * 8 + 2 * tgid;
            int c0 = n0 + lc;
            float bb0 = bias[c0], bb1 = bias[c0 + 1];
            float v00 = acc[mt][nt][0] + bb0, v01 = acc[mt][nt][1] + bb1;
            float v10 = acc[mt][nt][2] + bb0, v11 = acc[mt][nt][3] + bb1;
            int bb_ = r0 >> 10, key = r0 & 1023;
            int bh  = bb_ * HEADS + h;
            if (region == 0) {
                const float qs = 0.125f * LOG2E;
                size_t a0 = (size_t)(bb_ * N_TOK + key) * D_MODEL + h * 64 + lc;
                *(uint32_t*)(qp + a0)                 = pkbf(v00 * qs, v01 * qs);
                *(uint32_t*)(qp + a0 + 8 * D_MODEL)   = pkbf(v10 * qs, v11 * qs);
            } else if (region == 1) {
                size_t a0 = (size_t)(bh * N_TOK + key) * 64 + lc;
                *(uint32_t*)(kp + a0)        = pkbf(v00, v01);
                *(uint32_t*)(kp + a0 + 512)  = pkbf(v10, v11);
            } else {
                size_t a0 = (size_t)(bh * 64 + lc) * N_TOK + key;
                vtp[a0]              = __float2bfloat16(v00);
                vtp[a0 + N_TOK]      = __float2bfloat16(v01);
                vtp[a0 + 8]          = __float2bfloat16(v10);
                vtp[a0 + N_TOK + 8]  = __float2bfloat16(v11);
            }
        }
    }
}

// ---------------- bf16 mma flash attention: split-KV, register-P, smem dist -----
// 256 threads = 8 warps; warps 0-3 keys [0,32) per tile, warps 4-7 keys [32,64).
// Distance bias streamed as precomputed bf16 tiles (shared across all 8 heads);
// unpack is two bit-ops per pair (bf16->f32 = shift). No-max exp2 softmax; exact
// cross-group merge. smem: Ks[2]@0 16K, Vs@16384 16K, Qstage@32768 8K,
// Ds[2][8KB]@40960 16K => 57344 B.
__global__ void __launch_bounds__(256) attn_bf16(
        const __nv_bfloat16* __restrict__ qp, const __nv_bfloat16* __restrict__ kp,
        const __nv_bfloat16* __restrict__ vtp, const __nv_bfloat16* __restrict__ db,
        const float* __restrict__ w_edge, __half* __restrict__ out) {
    extern __shared__ char smb[];
    const uint32_t S0 = (uint32_t)__cvta_generic_to_shared(smb);
    const uint32_t OKS = S0, OVS = S0 + 16384, OPS = S0 + 32768;
    const uint32_t ODS = S0 + 40960;

    const int b = blockIdx.z, h = blockIdx.y, n0 = blockIdx.x * 64;
    const int bh = b * HEADS + h;
    const int tid = threadIdx.x, warp = tid >> 5, lane = tid & 31;
    const int kgrp = warp >> 2, wq = warp & 3;
    const int g = lane >> 2, t = lane & 3;
    const int l7 = lane & 7, sel = lane >> 3;
    const float we2 = w_edge[2 * HEADS + h] * LOG2E;

    const uint32_t bone = (lane < 4) ? 0x3F803F80u : 0u;
    const uint32_t bones[2] = {bone, bone};

    auto issue = [&](int buf, int m0) {
        #pragma unroll
        for (int u = 0; u < 2; u++) {
            int f = tid + u * 256; int r = f >> 3; int c = f & 7;
            uint32_t off = (uint32_t)(buf * 8192 + r * 128 + ((c ^ (r & 7)) << 4));
            cp16(OKS + off, kp  + (size_t)(bh * N_TOK + m0 + r) * 64 + c * 8);
            cp16(OVS + off, vtp + (size_t)(bh * 64 + r) * N_TOK + m0 + c * 8);
            cp16(ODS + off, db  + (size_t)(b * N_TOK + n0 + r) * N_TOK + m0 + c * 8);
        }
    };

    issue(0, 0);
    #pragma unroll
    for (int u = 0; u < 2; u++) {
        int f = tid + u * 256; int r = f >> 3; int c = f & 7;
        cp16(OPS + (uint32_t)(r * 128 + ((c ^ (r & 7)) << 4)),
             qp + (size_t)(b * N_TOK + n0 + r) * D_MODEL + h * 64 + c * 8);
    }
    cp_commit();
    cp_wait<0>();
    __syncthreads();

    uint32_t Qf[4][4];
    {
        const int row = wq * 16 + l7 + ((sel & 1) << 3);
        #pragma unroll
        for (int ks = 0; ks < 4; ks++) {
            int chunk = 2 * ks + (sel >> 1);
            ldmx4(Qf[ks], OPS + (uint32_t)(row * 128 + ((chunk ^ (row & 7)) << 4)));
        }
    }

    float O[8][4];
    #pragma unroll
    for (int nt = 0; nt < 8; nt++)
        #pragma unroll
        for (int e = 0; e < 4; e++) O[nt][e] = 0.0f;
    float Ox[4] = {0.0f, 0.0f, 0.0f, 0.0f};

    // this thread's dist rows (q rows wq*16+g and +8); row&7 == g for both
    const char* Dbase = smb + 40960;
    const int drow0 = (wq * 16 + g) * 128;
    const int drow1 = (wq * 16 + g + 8) * 128;

    for (int it = 0; it < 16; it++) {
        const int buf = it & 1;
        if (it + 1 < 16) { issue(buf ^ 1, (it + 1) * 64); cp_commit(); cp_wait<1>(); }
        else cp_wait<0>();
        __syncthreads();

        const char* Dsb = Dbase + buf * 8192;

        // S = Q @ K^T over this group's 32 keys
        float S[4][4];
        #pragma unroll
        for (int nt = 0; nt < 4; nt++)
            #pragma unroll
            for (int e = 0; e < 4; e++) S[nt][e] = 0.0f;
        #pragma unroll
        for (int ks = 0; ks < 4; ks++) {
            #pragma unroll
            for (int np = 0; np < 2; np++) {
                uint32_t Kf[4];
                int row = kgrp * 32 + np * 16 + l7 + ((sel >> 1) << 3);
                int chunk = 2 * ks + (sel & 1);
                ldmx4(Kf, OKS + (uint32_t)(buf * 8192 + row * 128 +
                                           ((chunk ^ (row & 7)) << 4)));
                mma_bf16(S[2 * np],     Qf[ks], Kf);
                mma_bf16(S[2 * np + 1], Qf[ks], Kf + 2);
            }
        }

        // dist bias (bf16 from smem; unpack = shift) + P = exp2(S), register A-frags
        uint32_t Pp[4][2];
        #pragma unroll
        for (int nt = 0; nt < 4; nt++) {
            int w = kgrp * 16 + nt * 4 + t;             // word index in 32-word row
            uint32_t woff = (uint32_t)((w ^ (g << 2)) << 2);
            uint32_t u0 = *(const uint32_t*)(Dsb + drow0 + woff);
            uint32_t u1 = *(const uint32_t*)(Dsb + drow1 + woff);
            float d00 = __uint_as_float(u0 << 16);
            float d01 = __uint_as_float(u0 & 0xffff0000u);
            float d10 = __uint_as_float(u1 << 16);
            float d11 = __uint_as_float(u1 & 0xffff0000u);
            Pp[nt][0] = ex2bf(pkbf(fmaf(d00, we2, S[nt][0]),
                                   fmaf(d01, we2, S[nt][1])));
            Pp[nt][1] = ex2bf(pkbf(fmaf(d10, we2, S[nt][2]),
                                   fmaf(d11, we2, S[nt][3])));
        }

        // O += P @ V ; Ox += P @ ones — P directly from registers
        #pragma unroll
        for (int kk = 0; kk < 2; kk++) {
            uint32_t Pa[4] = {Pp[2 * kk][0], Pp[2 * kk][1],
                              Pp[2 * kk + 1][0], Pp[2 * kk + 1][1]};
            #pragma unroll
            for (int dp = 0; dp < 4; dp++) {
                uint32_t Vf[4];
                int row = dp * 16 + l7 + ((sel >> 1) << 3);
                int chunk = kgrp * 4 + 2 * kk + (sel & 1);
                ldmx4(Vf, OVS + (uint32_t)(buf * 8192 + row * 128 +
                                           ((chunk ^ (row & 7)) << 4)));
                mma_bf16(O[2 * dp],     Pa, Vf);
                mma_bf16(O[2 * dp + 1], Pa, Vf + 2);
            }
            mma_bf16(Ox, Pa, bones);
        }
        __syncthreads();
    }

    // exact cross-group merge through smem (reuses K/V buffers; conflict-free)
    float* mbuf = (float*)smb;
    const int slot = wq * 32 + lane;           // 0..127 within each group
    if (kgrp) {
        #pragma unroll
        for (int nt = 0; nt < 8; nt++)
            #pragma unroll
            for (int e = 0; e < 4; e++)
                mbuf[(nt * 4 + e) * 128 + slot] = O[nt][e];
        mbuf[32 * 128 + slot] = Ox[0];
        mbuf[33 * 128 + slot] = Ox[2];
    }
    __syncthreads();
    if (!kgrp) {
        #pragma unroll
        for (int nt = 0; nt < 8; nt++)
            #pragma unroll
            for (int e = 0; e < 4; e++)
                O[nt][e] += mbuf[(nt * 4 + e) * 128 + slot];
        float ox0 = Ox[0] + mbuf[32 * 128 + slot];
        float ox2 = Ox[2] + mbuf[33 * 128 + slot];
        const int src = lane & 28;
        const float l0 = __shfl_sync(0xffffffffu, ox0, src);
        const float l1 = __shfl_sync(0xffffffffu, ox2, src);
        const float i0 = 1.0f / l0, i1 = 1.0f / l1;
        #pragma unroll
        for (int nt = 0; nt < 8; nt++) {
            int col = h * 64 + nt * 8 + 2 * t;
            size_t r0 = (size_t)(b * N_TOK + n0 + wq * 16 + g) * D_MODEL + col;
            *(uint32_t*)(out + r0)               = pkhf(O[nt][0] * i0, O[nt][1] * i0);
            *(uint32_t*)(out + r0 + 8 * D_MODEL) = pkhf(O[nt][2] * i1, O[nt][3] * i1);
        }
    }
}

// ---------------- launch ---------------------------------------------------------
extern "C" void kernel_launch(void* const* d_in, const int* in_sizes, int n_in,
                              void* d_out, int out_size) {
    const float* x      = (const float*)d_in[0];
    const float* coords = (const float*)d_in[1];
    const float* ln1g = (const float*)d_in[3];
    const float* ln1b = (const float*)d_in[4];
    const float* wqkv = (const float*)d_in[5];
    const float* bqkv = (const float*)d_in[6];
    const float* wedge= (const float*)d_in[7];
    const float* wout = (const float*)d_in[8];
    const float* bout = (const float*)d_in[9];
    const float* ln2g = (const float*)d_in[10];
    const float* ln2b = (const float*)d_in[11];
    const float* w1   = (const float*)d_in[12];
    const float* b1   = (const float*)d_in[13];
    const float* w2   = (const float*)d_in[14];
    const float* b2   = (const float*)d_in[15];
    float* out = (float*)d_out;

    void *p;
    float *x2;
    __half *xln16, *att16, *hid16, *wqkv_t, *wout_t, *w1_t, *w2_t;
    __nv_bfloat16 *qp, *kp, *vtp, *db;
    cudaGetSymbolAddress(&p, g_xln16);  xln16  = (__half*)p;
    cudaGetSymbolAddress(&p, g_qp);     qp     = (__nv_bfloat16*)p;
    cudaGetSymbolAddress(&p, g_kp);     kp     = (__nv_bfloat16*)p;
    cudaGetSymbolAddress(&p, g_vtp);    vtp    = (__nv_bfloat16*)p;
    cudaGetSymbolAddress(&p, g_db);     db     = (__nv_bfloat16*)p;
    cudaGetSymbolAddress(&p, g_att16);  att16  = (__half*)p;
    cudaGetSymbolAddress(&p, g_x2);     x2     = (float*)p;
    cudaGetSymbolAddress(&p, g_hid16);  hid16  = (__half*)p;
    cudaGetSymbolAddress(&p, g_wqkv_t); wqkv_t = (__half*)p;
    cudaGetSymbolAddress(&p, g_wout_t); wout_t = (__half*)p;
    cudaGetSymbolAddress(&p, g_w1_t);   w1_t   = (__half*)p;
    cudaGetSymbolAddress(&p, g_w2_t);   w2_t   = (__half*)p;

    const int ATTN_SMEM  = 57344;
    const int G16_SMEM_L = 2 * 128 * 128 + 2 * 8192;   // 49152
    const int G16_SMEM_S = 2 * 64 * 128 + 2 * 8192;    // 32768
    cudaFuncSetAttribute(attn_bf16, cudaFuncAttributeMaxDynamicSharedMemorySize, ATTN_SMEM);
    cudaFuncSetAttribute(gemm_qkv,  cudaFuncAttributeMaxDynamicSharedMemorySize, G16_SMEM_L);
    cudaFuncSetAttribute(gemm_f16<128,1>, cudaFuncAttributeMaxDynamicSharedMemorySize, G16_SMEM_L);
    cudaFuncSetAttribute(gemm_f16<64,0>,  cudaFuncAttributeMaxDynamicSharedMemorySize, G16_SMEM_S);

    // 0) prep: weight pack + LN1 + pairwise dist (one launch)
    prep_kernel<<<768 + 2048 + 2048, 256>>>(
        wqkv, wout, w1, w2, wqkv_t, wout_t, w1_t, w2_t,
        x, ln1g, ln1b, xln16, coords, db);
    // 1) QKV fp16 GEMM + fused bf16 pack
    gemm_qkv<<<dim3(1536/64, M_ROWS/128), 128, G16_SMEM_L>>>(
        xln16, wqkv_t, bqkv, qp, kp, vtp, 1536, D_MODEL);
    // 2) attention (bf16 mma, split-KV, register-P, smem dist) -> fp16 att
    attn_bf16<<<dim3(N_TOK/64, HEADS, BATCH), 256, ATTN_SMEM>>>(
        qp, kp, vtp, db, wedge, att16);
    // 3) out proj + residual(token_embs) -> x2 fp32
    gemm_f16<64,0><<<dim3(D_MODEL/64, M_ROWS/64), 128, G16_SMEM_S>>>(
        att16, wout_t, bout, x, x2, M_ROWS, D_MODEL, D_MODEL, 0);
    // 4) LN2 (fp16 out)
    ln_kernel<<<M_ROWS, 256>>>(x2, ln2g, ln2b, xln16);
    // 5) fc1 + gelu -> hid fp16
    gemm_f16<128,1><<<dim3(HIDDEN/64, M_ROWS/128), 128, G16_SMEM_L>>>(
        xln16, w1_t, b1, nullptr, hid16, M_ROWS, HIDDEN, D_MODEL, 1);
    // 6) fc2 + residual(x2) -> out fp32
    gemm_f16<64,0><<<dim3(D_MODEL/64, M_ROWS/64), 128, G16_SMEM_S>>>(
        hid16, w2_t, b2, x2, out, M_ROWS, D_MODEL, HIDDEN, 0);
}

// round 15
// speedup vs baseline: 1.1162x; 1.0109x over previous
#include <cuda_runtime.h>
#include <cuda_bf16.h>
#include <cuda_fp16.h>
#include <math.h>
#include <stdint.h>

#define D_MODEL 512
#define N_TOK   1024
#define BATCH   2
#define HEADS   8
#define HIDDEN  2048
#define M_ROWS  (BATCH * N_TOK)   // 2048
#define LOG2E 1.4426950408889634f

// ---------------- scratch (static device globals; no allocation) ----------------
__device__ __align__(256) __half g_xln16[M_ROWS * D_MODEL];                 // LN out fp16
__device__ __align__(256) __nv_bfloat16 g_qp [M_ROWS * D_MODEL];            // Q bf16 pre-scaled
__device__ __align__(256) __nv_bfloat16 g_kp [BATCH * HEADS * N_TOK * 64];  // K [bh][key][d]
__device__ __align__(256) __nv_bfloat16 g_vtp[BATCH * HEADS * 64 * N_TOK];  // V^T [bh][d][key]
__device__ __align__(256) __nv_bfloat16 g_db [BATCH * N_TOK * N_TOK];       // dist bf16 (4MB, L2)
__device__ __align__(256) __half g_att16[M_ROWS * D_MODEL];                 // attn out fp16
__device__ __align__(256) float  g_x2 [M_ROWS * D_MODEL];
__device__ __align__(256) __half g_hid16[M_ROWS * HIDDEN];
// transposed fp16 weights [N][K]
__device__ __align__(256) __half g_wqkv_t[1536 * 512];
__device__ __align__(256) __half g_wout_t[512 * 512];
__device__ __align__(256) __half g_w1_t  [2048 * 512];
__device__ __align__(256) __half g_w2_t  [512 * 2048];

// ---------------- helpers --------------------------------------------------------
__device__ __forceinline__ void cp16(uint32_t smem, const void* g) {
    asm volatile("cp.async.cg.shared.global [%0], [%1], 16;" :: "r"(smem), "l"(g));
}
__device__ __forceinline__ void cp_commit() { asm volatile("cp.async.commit_group;"); }
template<int N> __device__ __forceinline__ void cp_wait() {
    asm volatile("cp.async.wait_group %0;" :: "n"(N));
}
__device__ __forceinline__ uint32_t pkbf(float a, float b) {
    __nv_bfloat162 h = __floats2bfloat162_rn(a, b);
    return *(uint32_t*)&h;
}
__device__ __forceinline__ uint32_t pkhf(float a, float b) {
    __half2 h = __floats2half2_rn(a, b);
    return *(uint32_t*)&h;
}
__device__ __forceinline__ uint32_t ex2bf(uint32_t x) {
    uint32_t r; asm("ex2.approx.ftz.bf16x2 %0, %1;" : "=r"(r) : "r"(x)); return r;
}
__device__ __forceinline__ void mma_f16(float c[4], const uint32_t a[4], const uint32_t b[2]) {
    asm volatile(
        "mma.sync.aligned.m16n8k16.row.col.f32.f16.f16.f32 "
        "{%0,%1,%2,%3}, {%4,%5,%6,%7}, {%8,%9}, {%0,%1,%2,%3};"
        : "+f"(c[0]), "+f"(c[1]), "+f"(c[2]), "+f"(c[3])
        : "r"(a[0]), "r"(a[1]), "r"(a[2]), "r"(a[3]), "r"(b[0]), "r"(b[1]));
}
__device__ __forceinline__ void mma_bf16(float c[4], const uint32_t a[4], const uint32_t b[2]) {
    asm volatile(
        "mma.sync.aligned.m16n8k16.row.col.f32.bf16.bf16.f32 "
        "{%0,%1,%2,%3}, {%4,%5,%6,%7}, {%8,%9}, {%0,%1,%2,%3};"
        : "+f"(c[0]), "+f"(c[1]), "+f"(c[2]), "+f"(c[3])
        : "r"(a[0]), "r"(a[1]), "r"(a[2]), "r"(a[3]), "r"(b[0]), "r"(b[1]));
}
__device__ __forceinline__ void ldmx4(uint32_t r[4], uint32_t addr) {
    asm volatile("ldmatrix.sync.aligned.m8n8.x4.shared.b16 {%0,%1,%2,%3}, [%4];"
                 : "=r"(r[0]), "=r"(r[1]), "=r"(r[2]), "=r"(r[3]) : "r"(addr));
}
__device__ __forceinline__ float sqrt_approx(float x) {
    float r; asm("sqrt.approx.f32 %0, %1;" : "=f"(r) : "f"(x)); return r;
}

// ---------------- prep: weight pack + LN1 + pairwise dist (one launch) -----------
__global__ void prep_kernel(
        const float* __restrict__ wqkv, const float* __restrict__ wout,
        const float* __restrict__ w1, const float* __restrict__ w2,
        __half* __restrict__ wqkv_t, __half* __restrict__ wout_t,
        __half* __restrict__ w1_t, __half* __restrict__ w2_t,
        const float* __restrict__ x, const float* __restrict__ g1,
        const float* __restrict__ b1, __half* __restrict__ xln16,
        const float* __restrict__ coords, __nv_bfloat16* __restrict__ db) {
    const int bx = blockIdx.x, tid = threadIdx.x;

    if (bx < 768) {               // ---- weight pack ----
        __shared__ float tile[64][65];
        const float* src; __half* dst; int K, N, tk, tn;
        if (bx < 192)      { src = wqkv; dst = wqkv_t; K = 512;  N = 1536; int t = bx;       tk = t & 7;  tn = t >> 3; }
        else if (bx < 256) { src = wout; dst = wout_t; K = 512;  N = 512;  int t = bx - 192; tk = t & 7;  tn = t >> 3; }
        else if (bx < 512) { src = w1;   dst = w1_t;   K = 512;  N = 2048; int t = bx - 256; tk = t & 7;  tn = t >> 3; }
        else               { src = w2;   dst = w2_t;   K = 2048; N = 512;  int t = bx - 512; tk = t & 31; tn = t >> 5; }
        const int k0 = tk * 64, n0 = tn * 64;

        #pragma unroll
        for (int u = 0; u < 4; u++) {
            int f = tid + u * 256;
            int kr = f >> 4, nc = (f & 15) * 4;
            float4 v = *(const float4*)(src + (size_t)(k0 + kr) * N + n0 + nc);
            tile[nc + 0][kr] = v.x;
            tile[nc + 1][kr] = v.y;
            tile[nc + 2][kr] = v.z;
            tile[nc + 3][kr] = v.w;
        }
        __syncthreads();
        #pragma unroll
        for (int u = 0; u < 2; u++) {
            int f = tid + u * 256;
            int nr = f >> 3, kc = (f & 7) * 8;
            uint4 o;
            o.x = pkhf(tile[nr][kc + 0], tile[nr][kc + 1]);
            o.y = pkhf(tile[nr][kc + 2], tile[nr][kc + 3]);
            o.z = pkhf(tile[nr][kc + 4], tile[nr][kc + 5]);
            o.w = pkhf(tile[nr][kc + 6], tile[nr][kc + 7]);
            *(uint4*)(dst + (size_t)(n0 + nr) * K + k0 + kc) = o;
        }
    } else if (bx < 2816) {       // ---- LN1 ----
        __shared__ float sh[8], sh2[8];
        const int row = bx - 768;
        const float* xr = x + (size_t)row * D_MODEL;
        float v0 = xr[tid], v1 = xr[tid + 256];
        int w = tid >> 5, lane = tid & 31;

        float s = v0 + v1;
        #pragma unroll
        for (int o = 16; o; o >>= 1) s += __shfl_xor_sync(0xffffffffu, s, o);
        if (lane == 0) sh[w] = s;
        __syncthreads();
        float mean = (sh[0]+sh[1]+sh[2]+sh[3]+sh[4]+sh[5]+sh[6]+sh[7]) * (1.0f / D_MODEL);

        float d0 = v0 - mean, d1 = v1 - mean;
        float q = d0 * d0 + d1 * d1;
        #pragma unroll
        for (int o = 16; o; o >>= 1) q += __shfl_xor_sync(0xffffffffu, q, o);
        if (lane == 0) sh2[w] = q;
        __syncthreads();
        float var = (sh2[0]+sh2[1]+sh2[2]+sh2[3]+sh2[4]+sh2[5]+sh2[6]+sh2[7]) * (1.0f / D_MODEL);
        float inv = rsqrtf(var + 1e-5f);

        __half* yr = xln16 + (size_t)row * D_MODEL;
        yr[tid]       = __float2half(d0 * inv * g1[tid]       + b1[tid]);
        yr[tid + 256] = __float2half(d1 * inv * g1[tid + 256] + b1[tid + 256]);
    } else {                      // ---- pairwise distances (bf16) ----
        const int idx = bx - 2816;
        const int b = idx >> 10, n = idx & 1023;
        float2 q = ((const float2*)coords)[b * N_TOK + n];
        const int m0 = tid * 4;
        const float4* cp4 = (const float4*)(coords + (size_t)b * N_TOK * 2);
        float4 ca = cp4[m0 >> 1];
        float4 cb = cp4[(m0 >> 1) + 1];
        float dx, dy, d0, d1, d2, d3;
        dx = q.x - ca.x; dy = q.y - ca.y; d0 = sqrt_approx(dx*dx + dy*dy);
        dx = q.x - ca.z; dy = q.y - ca.w; d1 = sqrt_approx(dx*dx + dy*dy);
        dx = q.x - cb.x; dy = q.y - cb.y; d2 = sqrt_approx(dx*dx + dy*dy);
        dx = q.x - cb.z; dy = q.y - cb.w; d3 = sqrt_approx(dx*dx + dy*dy);
        uint2 o;
        o.x = pkbf(d0, d1);
        o.y = pkbf(d2, d3);
        *(uint2*)(db + (size_t)(b * N_TOK + n) * N_TOK + m0) = o;
    }
}

// ---------------- LayerNorm (fp32 in, fp16 out) ----------------------------------
__global__ void ln_kernel(const float* __restrict__ x, const float* __restrict__ g,
                          const float* __restrict__ b, __half* __restrict__ y) {
    int row = blockIdx.x;
    const float* xr = x + (size_t)row * D_MODEL;
    int t = threadIdx.x;
    float v0 = xr[t];
    float v1 = xr[t + 256];

    __shared__ float sh[8], sh2[8];
    int w = t >> 5, lane = t & 31;

    float s = v0 + v1;
    #pragma unroll
    for (int o = 16; o; o >>= 1) s += __shfl_xor_sync(0xffffffffu, s, o);
    if (lane == 0) sh[w] = s;
    __syncthreads();
    float mean = (sh[0]+sh[1]+sh[2]+sh[3]+sh[4]+sh[5]+sh[6]+sh[7]) * (1.0f / D_MODEL);

    float d0 = v0 - mean, d1 = v1 - mean;
    float q = d0 * d0 + d1 * d1;
    #pragma unroll
    for (int o = 16; o; o >>= 1) q += __shfl_xor_sync(0xffffffffu, q, o);
    if (lane == 0) sh2[w] = q;
    __syncthreads();
    float var = (sh2[0]+sh2[1]+sh2[2]+sh2[3]+sh2[4]+sh2[5]+sh2[6]+sh2[7]) * (1.0f / D_MODEL);
    float inv = rsqrtf(var + 1e-5f);

    __half* yr = y + (size_t)row * D_MODEL;
    yr[t]       = __float2half(d0 * inv * g[t]       + b[t]);
    yr[t + 256] = __float2half(d1 * inv * g[t + 256] + b[t + 256]);
}

// ---------------- fp16 GEMM mainloop: 3-stage cp.async pipeline ------------------
// A [M][K] fp16 row-major, Bt [N][K] fp16 row-major. BK=64. 4 warps 2x2.
#define GEMM16_BODY(A_, Bt_, K_)                                                   \
    constexpr int WM = BM / 2;                                                     \
    constexpr int MT = WM / 16;                                                    \
    extern __shared__ char smc[];                                                  \
    const uint32_t S0 = (uint32_t)__cvta_generic_to_shared(smc);                   \
    const uint32_t OAS = S0;                                                       \
    const uint32_t OBS = S0 + 3 * BM * 128;                                        \
    const int tid  = threadIdx.x;                                                  \
    const int warp = tid >> 5;                                                     \
    const int lane = tid & 31;                                                     \
    const int gpid = lane >> 2;                                                    \
    const int tgid = lane & 3;                                                     \
    const int l7   = lane & 7;                                                     \
    const int sel  = lane >> 3;                                                    \
    const int wm = warp >> 1;                                                      \
    const int wn = warp & 1;                                                       \
    const int m0 = blockIdx.y * BM;                                                \
    const int n0 = blockIdx.x * 64;                                                \
    float acc[MT][4][4];                                                           \
    _Pragma("unroll")                                                              \
    for (int i = 0; i < MT; i++)                                                   \
        _Pragma("unroll")                                                          \
        for (int j = 0; j < 4; j++)                                                \
            _Pragma("unroll")                                                      \
            for (int e = 0; e < 4; e++) acc[i][j][e] = 0.0f;                       \
    auto loadA = [&](int buf, int k0) {                                            \
        _Pragma("unroll")                                                          \
        for (int u = 0; u < BM / 16; u++) {                                        \
            int r = (tid >> 3) + u * 16; int g = tid & 7;                          \
            cp16(OAS + (uint32_t)(buf * BM * 128 + r * 128 + ((g ^ (r & 7)) << 4)),\
                 A_ + (size_t)(m0 + r) * K_ + k0 + g * 8);                         \
        }                                                                          \
    };                                                                             \
    auto loadB = [&](int buf, int k0) {                                            \
        _Pragma("unroll")                                                          \
        for (int u = 0; u < 4; u++) {                                              \
            int r = (tid >> 3) + u * 16; int g = tid & 7;                          \
            cp16(OBS + (uint32_t)(buf * 8192 + r * 128 + ((g ^ (r & 7)) << 4)),    \
                 Bt_ + (size_t)(n0 + r) * K_ + k0 + g * 8);                        \
        }                                                                          \
    };                                                                             \
    const int tiles = K_ >> 6;                                                     \
    loadA(0, 0); loadB(0, 0); cp_commit();                                         \
    if (tiles > 1) { loadA(1, 64); loadB(1, 64); cp_commit(); }                    \
    int cbuf = 0;                                                                  \
    for (int kt = 0; kt < tiles; kt++) {                                           \
        if (kt + 2 < tiles) {                                                      \
            int nb = cbuf + 2; if (nb >= 3) nb -= 3;                               \
            loadA(nb, (kt + 2) * 64);                                              \
            loadB(nb, (kt + 2) * 64);                                              \
            cp_commit(); cp_wait<2>();                                             \
        } else if (kt + 1 < tiles) { cp_wait<1>(); }                               \
        else { cp_wait<0>(); }                                                     \
        __syncthreads();                                                           \
        _Pragma("unroll")                                                          \
        for (int ks = 0; ks < 4; ks++) {                                           \
            uint32_t af[MT][4];                                                    \
            _Pragma("unroll")                                                      \
            for (int mt = 0; mt < MT; mt++) {                                      \
                int row = wm * WM + mt * 16 + l7 + ((sel & 1) << 3);               \
                int chunk = 2 * ks + (sel >> 1);                                   \
                ldmx4(af[mt], OAS + (uint32_t)(cbuf * BM * 128 + row * 128 +       \
                                               ((chunk ^ (row & 7)) << 4)));       \
            }                                                                      \
            uint32_t bf2[2][4];                                                    \
            _Pragma("unroll")                                                      \
            for (int np = 0; np < 2; np++) {                                       \
                int row = wn * 32 + np * 16 + l7 + ((sel >> 1) << 3);              \
                int chunk = 2 * ks + (sel & 1);                                    \
                ldmx4(bf2[np], OBS + (uint32_t)(cbuf * 8192 + row * 128 +          \
                                                ((chunk ^ (row & 7)) << 4)));      \
            }                                                                      \
            _Pragma("unroll")                                                      \
            for (int mt = 0; mt < MT; mt++) {                                      \
                mma_f16(acc[mt][0], af[mt], bf2[0]);                               \
                mma_f16(acc[mt][1], af[mt], bf2[0] + 2);                           \
                mma_f16(acc[mt][2], af[mt], bf2[1]);                               \
                mma_f16(acc[mt][3], af[mt], bf2[1] + 2);                           \
            }                                                                      \
        }                                                                          \
        __syncthreads();                                                           \
        if (++cbuf >= 3) cbuf = 0;                                                 \
    }

// ---------------- generic fp16 GEMM (bias; optional gelu/residual; f32/f16 out) --
template<int BM, int OUTF16>
__global__ void __launch_bounds__(128) gemm_f16(
        const __half* __restrict__ A, const __half* __restrict__ Bt,
        const float* __restrict__ bias, const float* __restrict__ res,
        void* __restrict__ Cout, int M, int Nn, int K, int do_gelu) {
    GEMM16_BODY(A, Bt, K)

    #pragma unroll
    for (int mt = 0; mt < MT; mt++) {
        #pragma unroll
        for (int nt = 0; nt < 4; nt++) {
            int r0 = m0 + wm * WM + mt * 16 + gpid;
            int c0 = n0 + wn * 32 + nt * 8 + 2 * tgid;
            float bb0 = bias[c0], bb1 = bias[c0 + 1];
            float v00 = acc[mt][nt][0] + bb0, v01 = acc[mt][nt][1] + bb1;
            float v10 = acc[mt][nt][2] + bb0, v11 = acc[mt][nt][3] + bb1;
            if (do_gelu) {
                v00 = 0.5f * v00 * (1.0f + erff(v00 * 0.70710678118654752f));
                v01 = 0.5f * v01 * (1.0f + erff(v01 * 0.70710678118654752f));
                v10 = 0.5f * v10 * (1.0f + erff(v10 * 0.70710678118654752f));
                v11 = 0.5f * v11 * (1.0f + erff(v11 * 0.70710678118654752f));
            }
            if (res) {
                v00 += res[(size_t)r0 * Nn + c0];
                v01 += res[(size_t)r0 * Nn + c0 + 1];
                v10 += res[(size_t)(r0 + 8) * Nn + c0];
                v11 += res[(size_t)(r0 + 8) * Nn + c0 + 1];
            }
            if (OUTF16) {
                __half* C = (__half*)Cout;
                *(uint32_t*)(C + (size_t)r0 * Nn + c0)       = pkhf(v00, v01);
                *(uint32_t*)(C + (size_t)(r0 + 8) * Nn + c0) = pkhf(v10, v11);
            } else {
                float* C = (float*)Cout;
                *(float2*)(C + (size_t)r0 * Nn + c0)       = make_float2(v00, v01);
                *(float2*)(C + (size_t)(r0 + 8) * Nn + c0) = make_float2(v10, v11);
            }
        }
    }
}

// ---------------- QKV fp16 GEMM with fused bf16 pack epilogue --------------------
__global__ void __launch_bounds__(128) gemm_qkv(
        const __half* __restrict__ A, const __half* __restrict__ Bt,
        const float* __restrict__ bias,
        __nv_bfloat16* __restrict__ qp, __nv_bfloat16* __restrict__ kp,
        __nv_bfloat16* __restrict__ vtp, int Nn, int K) {
    constexpr int BM = 128;
    GEMM16_BODY(A, Bt, K)

    const int region = n0 / 512;
    const int h = (n0 % 512) / 64;
    #pragma unroll
    for (int mt = 0; mt < MT; mt++) {
        #pragma unroll
        for (int nt = 0; nt < 4; nt++) {
            int r0 = m0 + wm * WM + mt * 16 + gpid;
            int lc = wn * 32 + nt * 8 + 2 * tgid;
            int c0 = n0 + lc;
            float bb0 = bias[c0], bb1 = bias[c0 + 1];
            float v00 = acc[mt][nt][0] + bb0, v01 = acc[mt][nt][1] + bb1;
            float v10 = acc[mt][nt][2] + bb0, v11 = acc[mt][nt][3] + bb1;
            int bb_ = r0 >> 10, key = r0 & 1023;
            int bh  = bb_ * HEADS + h;
            if (region == 0) {
                const float qs = 0.125f * LOG2E;
                size_t a0 = (size_t)(bb_ * N_TOK + key) * D_MODEL + h * 64 + lc;
                *(uint32_t*)(qp + a0)                 = pkbf(v00 * qs, v01 * qs);
                *(uint32_t*)(qp + a0 + 8 * D_MODEL)   = pkbf(v10 * qs, v11 * qs);
            } else if (region == 1) {
                size_t a0 = (size_t)(bh * N_TOK + key) * 64 + lc;
                *(uint32_t*)(kp + a0)        = pkbf(v00, v01);
                *(uint32_t*)(kp + a0 + 512)  = pkbf(v10, v11);
            } else {
                size_t a0 = (size_t)(bh * 64 + lc) * N_TOK + key;
                vtp[a0]              = __float2bfloat16(v00);
                vtp[a0 + N_TOK]      = __float2bfloat16(v01);
                vtp[a0 + 8]          = __float2bfloat16(v10);
                vtp[a0 + N_TOK + 8]  = __float2bfloat16(v11);
            }
        }
    }
}

// ---------------- bf16 mma flash attention: split-KV, register-P, smem dist -----
// (unchanged from R14)
__global__ void __launch_bounds__(256) attn_bf16(
        const __nv_bfloat16* __restrict__ qp, const __nv_bfloat16* __restrict__ kp,
        const __nv_bfloat16* __restrict__ vtp, const __nv_bfloat16* __restrict__ db,
        const float* __restrict__ w_edge, __half* __restrict__ out) {
    extern __shared__ char smb[];
    const uint32_t S0 = (uint32_t)__cvta_generic_to_shared(smb);
    const uint32_t OKS = S0, OVS = S0 + 16384, OPS = S0 + 32768;
    const uint32_t ODS = S0 + 40960;

    const int b = blockIdx.z, h = blockIdx.y, n0 = blockIdx.x * 64;
    const int bh = b * HEADS + h;
    const int tid = threadIdx.x, warp = tid >> 5, lane = tid & 31;
    const int kgrp = warp >> 2, wq = warp & 3;
    const int g = lane >> 2, t = lane & 3;
    const int l7 = lane & 7, sel = lane >> 3;
    const float we2 = w_edge[2 * HEADS + h] * LOG2E;

    const uint32_t bone = (lane < 4) ? 0x3F803F80u : 0u;
    const uint32_t bones[2] = {bone, bone};

    auto issue = [&](int buf, int m0) {
        #pragma unroll
        for (int u = 0; u < 2; u++) {
            int f = tid + u * 256; int r = f >> 3; int c = f & 7;
            uint32_t off = (uint32_t)(buf * 8192 + r * 128 + ((c ^ (r & 7)) << 4));
            cp16(OKS + off, kp  + (size_t)(bh * N_TOK + m0 + r) * 64 + c * 8);
            cp16(OVS + off, vtp + (size_t)(bh * 64 + r) * N_TOK + m0 + c * 8);
            cp16(ODS + off, db  + (size_t)(b * N_TOK + n0 + r) * N_TOK + m0 + c * 8);
        }
    };

    issue(0, 0);
    #pragma unroll
    for (int u = 0; u < 2; u++) {
        int f = tid + u * 256; int r = f >> 3; int c = f & 7;
        cp16(OPS + (uint32_t)(r * 128 + ((c ^ (r & 7)) << 4)),
             qp + (size_t)(b * N_TOK + n0 + r) * D_MODEL + h * 64 + c * 8);
    }
    cp_commit();
    cp_wait<0>();
    __syncthreads();

    uint32_t Qf[4][4];
    {
        const int row = wq * 16 + l7 + ((sel & 1) << 3);
        #pragma unroll
        for (int ks = 0; ks < 4; ks++) {
            int chunk = 2 * ks + (sel >> 1);
            ldmx4(Qf[ks], OPS + (uint32_t)(row * 128 + ((chunk ^ (row & 7)) << 4)));
        }
    }

    float O[8][4];
    #pragma unroll
    for (int nt = 0; nt < 8; nt++)
        #pragma unroll
        for (int e = 0; e < 4; e++) O[nt][e] = 0.0f;
    float Ox[4] = {0.0f, 0.0f, 0.0f, 0.0f};

    const char* Dbase = smb + 40960;
    const int drow0 = (wq * 16 + g) * 128;
    const int drow1 = (wq * 16 + g + 8) * 128;

    for (int it = 0; it < 16; it++) {
        const int buf = it & 1;
        if (it + 1 < 16) { issue(buf ^ 1, (it + 1) * 64); cp_commit(); cp_wait<1>(); }
        else cp_wait<0>();
        __syncthreads();

        const char* Dsb = Dbase + buf * 8192;

        float S[4][4];
        #pragma unroll
        for (int nt = 0; nt < 4; nt++)
            #pragma unroll
            for (int e = 0; e < 4; e++) S[nt][e] = 0.0f;
        #pragma unroll
        for (int ks = 0; ks < 4; ks++) {
            #pragma unroll
            for (int np = 0; np < 2; np++) {
                uint32_t Kf[4];
                int row = kgrp * 32 + np * 16 + l7 + ((sel >> 1) << 3);
                int chunk = 2 * ks + (sel & 1);
                ldmx4(Kf, OKS + (uint32_t)(buf * 8192 + row * 128 +
                                           ((chunk ^ (row & 7)) << 4)));
                mma_bf16(S[2 * np],     Qf[ks], Kf);
                mma_bf16(S[2 * np + 1], Qf[ks], Kf + 2);
            }
        }

        uint32_t Pp[4][2];
        #pragma unroll
        for (int nt = 0; nt < 4; nt++) {
            int w = kgrp * 16 + nt * 4 + t;
            uint32_t woff = (uint32_t)((w ^ (g << 2)) << 2);
            uint32_t u0 = *(const uint32_t*)(Dsb + drow0 + woff);
            uint32_t u1 = *(const uint32_t*)(Dsb + drow1 + woff);
            float d00 = __uint_as_float(u0 << 16);
            float d01 = __uint_as_float(u0 & 0xffff0000u);
            float d10 = __uint_as_float(u1 << 16);
            float d11 = __uint_as_float(u1 & 0xffff0000u);
            Pp[nt][0] = ex2bf(pkbf(fmaf(d00, we2, S[nt][0]),
                                   fmaf(d01, we2, S[nt][1])));
            Pp[nt][1] = ex2bf(pkbf(fmaf(d10, we2, S[nt][2]),
                                   fmaf(d11, we2, S[nt][3])));
        }

        #pragma unroll
        for (int kk = 0; kk < 2; kk++) {
            uint32_t Pa[4] = {Pp[2 * kk][0], Pp[2 * kk][1],
                              Pp[2 * kk + 1][0], Pp[2 * kk + 1][1]};
            #pragma unroll
            for (int dp = 0; dp < 4; dp++) {
                uint32_t Vf[4];
                int row = dp * 16 + l7 + ((sel >> 1) << 3);
                int chunk = kgrp * 4 + 2 * kk + (sel & 1);
                ldmx4(Vf, OVS + (uint32_t)(buf * 8192 + row * 128 +
                                           ((chunk ^ (row & 7)) << 4)));
                mma_bf16(O[2 * dp],     Pa, Vf);
                mma_bf16(O[2 * dp + 1], Pa, Vf + 2);
            }
            mma_bf16(Ox, Pa, bones);
        }
        __syncthreads();
    }

    float* mbuf = (float*)smb;
    const int slot = wq * 32 + lane;
    if (kgrp) {
        #pragma unroll
        for (int nt = 0; nt < 8; nt++)
            #pragma unroll
            for (int e = 0; e < 4; e++)
                mbuf[(nt * 4 + e) * 128 + slot] = O[nt][e];
        mbuf[32 * 128 + slot] = Ox[0];
        mbuf[33 * 128 + slot] = Ox[2];
    }
    __syncthreads();
    if (!kgrp) {
        #pragma unroll
        for (int nt = 0; nt < 8; nt++)
            #pragma unroll
            for (int e = 0; e < 4; e++)
                O[nt][e] += mbuf[(nt * 4 + e) * 128 + slot];
        float ox0 = Ox[0] + mbuf[32 * 128 + slot];
        float ox2 = Ox[2] + mbuf[33 * 128 + slot];
        const int src = lane & 28;
        const float l0 = __shfl_sync(0xffffffffu, ox0, src);
        const float l1 = __shfl_sync(0xffffffffu, ox2, src);
        const float i0 = 1.0f / l0, i1 = 1.0f / l1;
        #pragma unroll
        for (int nt = 0; nt < 8; nt++) {
            int col = h * 64 + nt * 8 + 2 * t;
            size_t r0 = (size_t)(b * N_TOK + n0 + wq * 16 + g) * D_MODEL + col;
            *(uint32_t*)(out + r0)               = pkhf(O[nt][0] * i0, O[nt][1] * i0);
            *(uint32_t*)(out + r0 + 8 * D_MODEL) = pkhf(O[nt][2] * i1, O[nt][3] * i1);
        }
    }
}

// ---------------- launch ---------------------------------------------------------
extern "C" void kernel_launch(void* const* d_in, const int* in_sizes, int n_in,
                              void* d_out, int out_size) {
    const float* x      = (const float*)d_in[0];
    const float* coords = (const float*)d_in[1];
    const float* ln1g = (const float*)d_in[3];
    const float* ln1b = (const float*)d_in[4];
    const float* wqkv = (const float*)d_in[5];
    const float* bqkv = (const float*)d_in[6];
    const float* wedge= (const float*)d_in[7];
    const float* wout = (const float*)d_in[8];
    const float* bout = (const float*)d_in[9];
    const float* ln2g = (const float*)d_in[10];
    const float* ln2b = (const float*)d_in[11];
    const float* w1   = (const float*)d_in[12];
    const float* b1   = (const float*)d_in[13];
    const float* w2   = (const float*)d_in[14];
    const float* b2   = (const float*)d_in[15];
    float* out = (float*)d_out;

    void *p;
    float *x2;
    __half *xln16, *att16, *hid16, *wqkv_t, *wout_t, *w1_t, *w2_t;
    __nv_bfloat16 *qp, *kp, *vtp, *db;
    cudaGetSymbolAddress(&p, g_xln16);  xln16  = (__half*)p;
    cudaGetSymbolAddress(&p, g_qp);     qp     = (__nv_bfloat16*)p;
    cudaGetSymbolAddress(&p, g_kp);     kp     = (__nv_bfloat16*)p;
    cudaGetSymbolAddress(&p, g_vtp);    vtp    = (__nv_bfloat16*)p;
    cudaGetSymbolAddress(&p, g_db);     db     = (__nv_bfloat16*)p;
    cudaGetSymbolAddress(&p, g_att16);  att16  = (__half*)p;
    cudaGetSymbolAddress(&p, g_x2);     x2     = (float*)p;
    cudaGetSymbolAddress(&p, g_hid16);  hid16  = (__half*)p;
    cudaGetSymbolAddress(&p, g_wqkv_t); wqkv_t = (__half*)p;
    cudaGetSymbolAddress(&p, g_wout_t); wout_t = (__half*)p;
    cudaGetSymbolAddress(&p, g_w1_t);   w1_t   = (__half*)p;
    cudaGetSymbolAddress(&p, g_w2_t);   w2_t   = (__half*)p;

    const int ATTN_SMEM  = 57344;
    const int G16_SMEM_L = 3 * (128 * 128 + 8192);   // 73728
    const int G16_SMEM_S = 3 * (64 * 128 + 8192);    // 49152
    cudaFuncSetAttribute(attn_bf16, cudaFuncAttributeMaxDynamicSharedMemorySize, ATTN_SMEM);
    cudaFuncSetAttribute(gemm_qkv,  cudaFuncAttributeMaxDynamicSharedMemorySize, G16_SMEM_L);
    cudaFuncSetAttribute(gemm_f16<128,1>, cudaFuncAttributeMaxDynamicSharedMemorySize, G16_SMEM_L);
    cudaFuncSetAttribute(gemm_f16<64,0>,  cudaFuncAttributeMaxDynamicSharedMemorySize, G16_SMEM_S);

    // 0) prep: weight pack + LN1 + pairwise dist (one launch)
    prep_kernel<<<768 + 2048 + 2048, 256>>>(
        wqkv, wout, w1, w2, wqkv_t, wout_t, w1_t, w2_t,
        x, ln1g, ln1b, xln16, coords, db);
    // 1) QKV fp16 GEMM + fused bf16 pack
    gemm_qkv<<<dim3(1536/64, M_ROWS/128), 128, G16_SMEM_L>>>(
        xln16, wqkv_t, bqkv, qp, kp, vtp, 1536, D_MODEL);
    // 2) attention (bf16 mma, split-KV, register-P, smem dist) -> fp16 att
    attn_bf16<<<dim3(N_TOK/64, HEADS, BATCH), 256, ATTN_SMEM>>>(
        qp, kp, vtp, db, wedge, att16);
    // 3) out proj + residual(token_embs) -> x2 fp32
    gemm_f16<64,0><<<dim3(D_MODEL/64, M_ROWS/64), 128, G16_SMEM_S>>>(
        att16, wout_t, bout, x, x2, M_ROWS, D_MODEL, D_MODEL, 0);
    // 4) LN2 (fp16 out)
    ln_kernel<<<M_ROWS, 256>>>(x2, ln2g, ln2b, xln16);
    // 5) fc1 + gelu -> hid fp16
    gemm_f16<128,1><<<dim3(HIDDEN/64, M_ROWS/128), 128, G16_SMEM_L>>>(
        xln16, w1_t, b1, nullptr, hid16, M_ROWS, HIDDEN, D_MODEL, 1);
    // 6) fc2 + residual(x2) -> out fp32
    gemm_f16<64,0><<<dim3(D_MODEL/64, M_ROWS/64), 128, G16_SMEM_S>>>(
        hid16, w2_t, b2, x2, out, M_ROWS, D_MODEL, HIDDEN, 0);
}

// round 16
// speedup vs baseline: 1.1273x; 1.0100x over previous
#include <cuda_runtime.h>
#include <cuda_bf16.h>
#include <cuda_fp16.h>
#include <math.h>
#include <stdint.h>

#define D_MODEL 512
#define N_TOK   1024
#define BATCH   2
#define HEADS   8
#define HIDDEN  2048
#define M_ROWS  (BATCH * N_TOK)   // 2048
#define LOG2E 1.4426950408889634f

// ---------------- scratch (static device globals; no allocation) ----------------
__device__ __align__(256) __half g_xln16[M_ROWS * D_MODEL];                 // LN out fp16
__device__ __align__(256) __nv_bfloat16 g_qp [M_ROWS * D_MODEL];            // Q bf16 pre-scaled
__device__ __align__(256) __nv_bfloat16 g_kp [BATCH * HEADS * N_TOK * 64];  // K [bh][key][d]
__device__ __align__(256) __nv_bfloat16 g_vtp[BATCH * HEADS * 64 * N_TOK];  // V^T [bh][d][key]
__device__ __align__(256) __nv_bfloat16 g_db [BATCH * N_TOK * N_TOK];       // dist bf16 (4MB, L2)
__device__ __align__(256) __half g_att16[M_ROWS * D_MODEL];                 // attn out fp16
__device__ __align__(256) float  g_x2 [M_ROWS * D_MODEL];
__device__ __align__(256) __half g_hid16[M_ROWS * HIDDEN];
// transposed fp16 weights [N][K]
__device__ __align__(256) __half g_wqkv_t[1536 * 512];
__device__ __align__(256) __half g_wout_t[512 * 512];
__device__ __align__(256) __half g_w1_t  [2048 * 512];
__device__ __align__(256) __half g_w2_t  [512 * 2048];

// ---------------- helpers --------------------------------------------------------
__device__ __forceinline__ void gdc_wait()   { asm volatile("griddepcontrol.wait;" ::: "memory"); }
__device__ __forceinline__ void gdc_launch() { asm volatile("griddepcontrol.launch_dependents;"); }
__device__ __forceinline__ void cp16(uint32_t smem, const void* g) {
    asm volatile("cp.async.cg.shared.global [%0], [%1], 16;" :: "r"(smem), "l"(g));
}
__device__ __forceinline__ void cp_commit() { asm volatile("cp.async.commit_group;"); }
template<int N> __device__ __forceinline__ void cp_wait() {
    asm volatile("cp.async.wait_group %0;" :: "n"(N));
}
__device__ __forceinline__ uint32_t pkbf(float a, float b) {
    __nv_bfloat162 h = __floats2bfloat162_rn(a, b);
    return *(uint32_t*)&h;
}
__device__ __forceinline__ uint32_t pkhf(float a, float b) {
    __half2 h = __floats2half2_rn(a, b);
    return *(uint32_t*)&h;
}
__device__ __forceinline__ uint32_t ex2bf(uint32_t x) {
    uint32_t r; asm("ex2.approx.ftz.bf16x2 %0, %1;" : "=r"(r) : "r"(x)); return r;
}
__device__ __forceinline__ void mma_f16(float c[4], const uint32_t a[4], const uint32_t b[2]) {
    asm volatile(
        "mma.sync.aligned.m16n8k16.row.col.f32.f16.f16.f32 "
        "{%0,%1,%2,%3}, {%4,%5,%6,%7}, {%8,%9}, {%0,%1,%2,%3};"
        : "+f"(c[0]), "+f"(c[1]), "+f"(c[2]), "+f"(c[3])
        : "r"(a[0]), "r"(a[1]), "r"(a[2]), "r"(a[3]), "r"(b[0]), "r"(b[1]));
}
__device__ __forceinline__ void mma_bf16(float c[4], const uint32_t a[4], const uint32_t b[2]) {
    asm volatile(
        "mma.sync.aligned.m16n8k16.row.col.f32.bf16.bf16.f32 "
        "{%0,%1,%2,%3}, {%4,%5,%6,%7}, {%8,%9}, {%0,%1,%2,%3};"
        : "+f"(c[0]), "+f"(c[1]), "+f"(c[2]), "+f"(c[3])
        : "r"(a[0]), "r"(a[1]), "r"(a[2]), "r"(a[3]), "r"(b[0]), "r"(b[1]));
}
__device__ __forceinline__ void ldmx4(uint32_t r[4], uint32_t addr) {
    asm volatile("ldmatrix.sync.aligned.m8n8.x4.shared.b16 {%0,%1,%2,%3}, [%4];"
                 : "=r"(r[0]), "=r"(r[1]), "=r"(r[2]), "=r"(r[3]) : "r"(addr));
}
__device__ __forceinline__ float sqrt_approx(float x) {
    float r; asm("sqrt.approx.f32 %0, %1;" : "=f"(r) : "f"(x)); return r;
}

// ---------------- prep: weight pack + LN1 + pairwise dist (one launch) -----------
__global__ void prep_kernel(
        const float* __restrict__ wqkv, const float* __restrict__ wout,
        const float* __restrict__ w1, const float* __restrict__ w2,
        __half* __restrict__ wqkv_t, __half* __restrict__ wout_t,
        __half* __restrict__ w1_t, __half* __restrict__ w2_t,
        const float* __restrict__ x, const float* __restrict__ g1,
        const float* __restrict__ b1, __half* __restrict__ xln16,
        const float* __restrict__ coords, __nv_bfloat16* __restrict__ db) {
    const int bx = blockIdx.x, tid = threadIdx.x;

    if (bx < 768) {               // ---- weight pack ----
        __shared__ float tile[64][65];
        const float* src; __half* dst; int K, N, tk, tn;
        if (bx < 192)      { src = wqkv; dst = wqkv_t; K = 512;  N = 1536; int t = bx;       tk = t & 7;  tn = t >> 3; }
        else if (bx < 256) { src = wout; dst = wout_t; K = 512;  N = 512;  int t = bx - 192; tk = t & 7;  tn = t >> 3; }
        else if (bx < 512) { src = w1;   dst = w1_t;   K = 512;  N = 2048; int t = bx - 256; tk = t & 7;  tn = t >> 3; }
        else               { src = w2;   dst = w2_t;   K = 2048; N = 512;  int t = bx - 512; tk = t & 31; tn = t >> 5; }
        const int k0 = tk * 64, n0 = tn * 64;

        #pragma unroll
        for (int u = 0; u < 4; u++) {
            int f = tid + u * 256;
            int kr = f >> 4, nc = (f & 15) * 4;
            float4 v = *(const float4*)(src + (size_t)(k0 + kr) * N + n0 + nc);
            tile[nc + 0][kr] = v.x;
            tile[nc + 1][kr] = v.y;
            tile[nc + 2][kr] = v.z;
            tile[nc + 3][kr] = v.w;
        }
        __syncthreads();
        #pragma unroll
        for (int u = 0; u < 2; u++) {
            int f = tid + u * 256;
            int nr = f >> 3, kc = (f & 7) * 8;
            uint4 o;
            o.x = pkhf(tile[nr][kc + 0], tile[nr][kc + 1]);
            o.y = pkhf(tile[nr][kc + 2], tile[nr][kc + 3]);
            o.z = pkhf(tile[nr][kc + 4], tile[nr][kc + 5]);
            o.w = pkhf(tile[nr][kc + 6], tile[nr][kc + 7]);
            *(uint4*)(dst + (size_t)(n0 + nr) * K + k0 + kc) = o;
        }
    } else if (bx < 2816) {       // ---- LN1 ----
        __shared__ float sh[8], sh2[8];
        const int row = bx - 768;
        const float* xr = x + (size_t)row * D_MODEL;
        float v0 = xr[tid], v1 = xr[tid + 256];
        int w = tid >> 5, lane = tid & 31;

        float s = v0 + v1;
        #pragma unroll
        for (int o = 16; o; o >>= 1) s += __shfl_xor_sync(0xffffffffu, s, o);
        if (lane == 0) sh[w] = s;
        __syncthreads();
        float mean = (sh[0]+sh[1]+sh[2]+sh[3]+sh[4]+sh[5]+sh[6]+sh[7]) * (1.0f / D_MODEL);

        float d0 = v0 - mean, d1 = v1 - mean;
        float q = d0 * d0 + d1 * d1;
        #pragma unroll
        for (int o = 16; o; o >>= 1) q += __shfl_xor_sync(0xffffffffu, q, o);
        if (lane == 0) sh2[w] = q;
        __syncthreads();
        float var = (sh2[0]+sh2[1]+sh2[2]+sh2[3]+sh2[4]+sh2[5]+sh2[6]+sh2[7]) * (1.0f / D_MODEL);
        float inv = rsqrtf(var + 1e-5f);

        __half* yr = xln16 + (size_t)row * D_MODEL;
        yr[tid]       = __float2half(d0 * inv * g1[tid]       + b1[tid]);
        yr[tid + 256] = __float2half(d1 * inv * g1[tid + 256] + b1[tid + 256]);
    } else {                      // ---- pairwise distances (bf16) ----
        const int idx = bx - 2816;
        const int b = idx >> 10, n = idx & 1023;
        float2 q = ((const float2*)coords)[b * N_TOK + n];
        const int m0 = tid * 4;
        const float4* cp4 = (const float4*)(coords + (size_t)b * N_TOK * 2);
        float4 ca = cp4[m0 >> 1];
        float4 cb = cp4[(m0 >> 1) + 1];
        float dx, dy, d0, d1, d2, d3;
        dx = q.x - ca.x; dy = q.y - ca.y; d0 = sqrt_approx(dx*dx + dy*dy);
        dx = q.x - ca.z; dy = q.y - ca.w; d1 = sqrt_approx(dx*dx + dy*dy);
        dx = q.x - cb.x; dy = q.y - cb.y; d2 = sqrt_approx(dx*dx + dy*dy);
        dx = q.x - cb.z; dy = q.y - cb.w; d3 = sqrt_approx(dx*dx + dy*dy);
        uint2 o;
        o.x = pkbf(d0, d1);
        o.y = pkbf(d2, d3);
        *(uint2*)(db + (size_t)(b * N_TOK + n) * N_TOK + m0) = o;
    }
    gdc_launch();
}

// ---------------- LayerNorm (fp32 in, fp16 out) ----------------------------------
__global__ void ln_kernel(const float* __restrict__ x, const float* __restrict__ g,
                          const float* __restrict__ b, __half* __restrict__ y) {
    gdc_wait();
    int row = blockIdx.x;
    const float* xr = x + (size_t)row * D_MODEL;
    int t = threadIdx.x;
    float v0 = xr[t];
    float v1 = xr[t + 256];

    __shared__ float sh[8], sh2[8];
    int w = t >> 5, lane = t & 31;

    float s = v0 + v1;
    #pragma unroll
    for (int o = 16; o; o >>= 1) s += __shfl_xor_sync(0xffffffffu, s, o);
    if (lane == 0) sh[w] = s;
    __syncthreads();
    float mean = (sh[0]+sh[1]+sh[2]+sh[3]+sh[4]+sh[5]+sh[6]+sh[7]) * (1.0f / D_MODEL);

    float d0 = v0 - mean, d1 = v1 - mean;
    float q = d0 * d0 + d1 * d1;
    #pragma unroll
    for (int o = 16; o; o >>= 1) q += __shfl_xor_sync(0xffffffffu, q, o);
    if (lane == 0) sh2[w] = q;
    __syncthreads();
    float var = (sh2[0]+sh2[1]+sh2[2]+sh2[3]+sh2[4]+sh2[5]+sh2[6]+sh2[7]) * (1.0f / D_MODEL);
    float inv = rsqrtf(var + 1e-5f);

    __half* yr = y + (size_t)row * D_MODEL;
    yr[t]       = __float2half(d0 * inv * g[t]       + b[t]);
    yr[t + 256] = __float2half(d1 * inv * g[t + 256] + b[t + 256]);
    gdc_launch();
}

// ---------------- fp16 GEMM mainloop: 3-stage cp.async pipeline ------------------
#define GEMM16_BODY(A_, Bt_, K_)                                                   \
    constexpr int WM = BM / 2;                                                     \
    constexpr int MT = WM / 16;                                                    \
    extern __shared__ char smc[];                                                  \
    const uint32_t S0 = (uint32_t)__cvta_generic_to_shared(smc);                   \
    const uint32_t OAS = S0;                                                       \
    const uint32_t OBS = S0 + 3 * BM * 128;                                        \
    const int tid  = threadIdx.x;                                                  \
    const int warp = tid >> 5;                                                     \
    const int lane = tid & 31;                                                     \
    const int gpid = lane >> 2;                                                    \
    const int tgid = lane & 3;                                                     \
    const int l7   = lane & 7;                                                     \
    const int sel  = lane >> 3;                                                    \
    const int wm = warp >> 1;                                                      \
    const int wn = warp & 1;                                                       \
    const int m0 = blockIdx.y * BM;                                                \
    const int n0 = blockIdx.x * 64;                                                \
    float acc[MT][4][4];                                                           \
    _Pragma("unroll")                                                              \
    for (int i = 0; i < MT; i++)                                                   \
        _Pragma("unroll")                                                          \
        for (int j = 0; j < 4; j++)                                                \
            _Pragma("unroll")                                                      \
            for (int e = 0; e < 4; e++) acc[i][j][e] = 0.0f;                       \
    auto loadA = [&](int buf, int k0) {                                            \
        _Pragma("unroll")                                                          \
        for (int u = 0; u < BM / 16; u++) {                                        \
            int r = (tid >> 3) + u * 16; int g = tid & 7;                          \
            cp16(OAS + (uint32_t)(buf * BM * 128 + r * 128 + ((g ^ (r & 7)) << 4)),\
                 A_ + (size_t)(m0 + r) * K_ + k0 + g * 8);                         \
        }                                                                          \
    };                                                                             \
    auto loadB = [&](int buf, int k0) {                                            \
        _Pragma("unroll")                                                          \
        for (int u = 0; u < 4; u++) {                                              \
            int r = (tid >> 3) + u * 16; int g = tid & 7;                          \
            cp16(OBS + (uint32_t)(buf * 8192 + r * 128 + ((g ^ (r & 7)) << 4)),    \
                 Bt_ + (size_t)(n0 + r) * K_ + k0 + g * 8);                        \
        }                                                                          \
    };                                                                             \
    const int tiles = K_ >> 6;                                                     \
    loadA(0, 0); loadB(0, 0); cp_commit();                                         \
    if (tiles > 1) { loadA(1, 64); loadB(1, 64); cp_commit(); }                    \
    int cbuf = 0;                                                                  \
    for (int kt = 0; kt < tiles; kt++) {                                           \
        if (kt + 2 < tiles) {                                                      \
            int nb = cbuf + 2; if (nb >= 3) nb -= 3;                               \
            loadA(nb, (kt + 2) * 64);                                              \
            loadB(nb, (kt + 2) * 64);                                              \
            cp_commit(); cp_wait<2>();                                             \
        } else if (kt + 1 < tiles) { cp_wait<1>(); }                               \
        else { cp_wait<0>(); }                                                     \
        __syncthreads();                                                           \
        _Pragma("unroll")                                                          \
        for (int ks = 0; ks < 4; ks++) {                                           \
            uint32_t af[MT][4];                                                    \
            _Pragma("unroll")                                                      \
            for (int mt = 0; mt < MT; mt++) {                                      \
                int row = wm * WM + mt * 16 + l7 + ((sel & 1) << 3);               \
                int chunk = 2 * ks + (sel >> 1);                                   \
                ldmx4(af[mt], OAS + (uint32_t)(cbuf * BM * 128 + row * 128 +       \
                                               ((chunk ^ (row & 7)) << 4)));       \
            }                                                                      \
            uint32_t bf2[2][4];                                                    \
            _Pragma("unroll")                                                      \
            for (int np = 0; np < 2; np++) {                                       \
                int row = wn * 32 + np * 16 + l7 + ((sel >> 1) << 3);              \
                int chunk = 2 * ks + (sel & 1);                                    \
                ldmx4(bf2[np], OBS + (uint32_t)(cbuf * 8192 + row * 128 +          \
                                                ((chunk ^ (row & 7)) << 4)));      \
            }                                                                      \
            _Pragma("unroll")                                                      \
            for (int mt = 0; mt < MT; mt++) {                                      \
                mma_f16(acc[mt][0], af[mt], bf2[0]);                               \
                mma_f16(acc[mt][1], af[mt], bf2[0] + 2);                           \
                mma_f16(acc[mt][2], af[mt], bf2[1]);                               \
                mma_f16(acc[mt][3], af[mt], bf2[1] + 2);                           \
            }                                                                      \
        }                                                                          \
        __syncthreads();                                                           \
        if (++cbuf >= 3) cbuf = 0;                                                 \
    }

// ---------------- generic fp16 GEMM (bias; optional gelu/residual; f32/f16 out) --
template<int BM, int OUTF16>
__global__ void __launch_bounds__(128) gemm_f16(
        const __half* __restrict__ A, const __half* __restrict__ Bt,
        const float* __restrict__ bias, const float* __restrict__ res,
        void* __restrict__ Cout, int M, int Nn, int K, int do_gelu) {
    gdc_wait();
    GEMM16_BODY(A, Bt, K)

    #pragma unroll
    for (int mt = 0; mt < MT; mt++) {
        #pragma unroll
        for (int nt = 0; nt < 4; nt++) {
            int r0 = m0 + wm * WM + mt * 16 + gpid;
            int c0 = n0 + wn * 32 + nt * 8 + 2 * tgid;
            float bb0 = bias[c0], bb1 = bias[c0 + 1];
            float v00 = acc[mt][nt][0] + bb0, v01 = acc[mt][nt][1] + bb1;
            float v10 = acc[mt][nt][2] + bb0, v11 = acc[mt][nt][3] + bb1;
            if (do_gelu) {
                v00 = 0.5f * v00 * (1.0f + erff(v00 * 0.70710678118654752f));
                v01 = 0.5f * v01 * (1.0f + erff(v01 * 0.70710678118654752f));
                v10 = 0.5f * v10 * (1.0f + erff(v10 * 0.70710678118654752f));
                v11 = 0.5f * v11 * (1.0f + erff(v11 * 0.70710678118654752f));
            }
            if (res) {
                v00 += res[(size_t)r0 * Nn + c0];
                v01 += res[(size_t)r0 * Nn + c0 + 1];
                v10 += res[(size_t)(r0 + 8) * Nn + c0];
                v11 += res[(size_t)(r0 + 8) * Nn + c0 + 1];
            }
            if (OUTF16) {
                __half* C = (__half*)Cout;
                *(uint32_t*)(C + (size_t)r0 * Nn + c0)       = pkhf(v00, v01);
                *(uint32_t*)(C + (size_t)(r0 + 8) * Nn + c0) = pkhf(v10, v11);
            } else {
                float* C = (float*)Cout;
                *(float2*)(C + (size_t)r0 * Nn + c0)       = make_float2(v00, v01);
                *(float2*)(C + (size_t)(r0 + 8) * Nn + c0) = make_float2(v10, v11);
            }
        }
    }
    gdc_launch();
}

// ---------------- QKV fp16 GEMM with fused bf16 pack epilogue --------------------
__global__ void __launch_bounds__(128) gemm_qkv(
        const __half* __restrict__ A, const __half* __restrict__ Bt,
        const float* __restrict__ bias,
        __nv_bfloat16* __restrict__ qp, __nv_bfloat16* __restrict__ kp,
        __nv_bfloat16* __restrict__ vtp, int Nn, int K) {
    gdc_wait();
    constexpr int BM = 128;
    GEMM16_BODY(A, Bt, K)

    const int region = n0 / 512;
    const int h = (n0 % 512) / 64;
    #pragma unroll
    for (int mt = 0; mt < MT; mt++) {
        #pragma unroll
        for (int nt = 0; nt < 4; nt++) {
            int r0 = m0 + wm * WM + mt * 16 + gpid;
            int lc = wn * 32 + nt * 8 + 2 * tgid;
            int c0 = n0 + lc;
            float bb0 = bias[c0], bb1 = bias[c0 + 1];
            float v00 = acc[mt][nt][0] + bb0, v01 = acc[mt][nt][1] + bb1;
            float v10 = acc[mt][nt][2] + bb0, v11 = acc[mt][nt][3] + bb1;
            int bb_ = r0 >> 10, key = r0 & 1023;
            int bh  = bb_ * HEADS + h;
            if (region == 0) {
                const float qs = 0.125f * LOG2E;
                size_t a0 = (size_t)(bb_ * N_TOK + key) * D_MODEL + h * 64 + lc;
                *(uint32_t*)(qp + a0)                 = pkbf(v00 * qs, v01 * qs);
                *(uint32_t*)(qp + a0 + 8 * D_MODEL)   = pkbf(v10 * qs, v11 * qs);
            } else if (region == 1) {
                size_t a0 = (size_t)(bh * N_TOK + key) * 64 + lc;
                *(uint32_t*)(kp + a0)        = pkbf(v00, v01);
                *(uint32_t*)(kp + a0 + 512)  = pkbf(v10, v11);
            } else {
                size_t a0 = (size_t)(bh * 64 + lc) * N_TOK + key;
                vtp[a0]              = __float2bfloat16(v00);
                vtp[a0 + N_TOK]      = __float2bfloat16(v01);
                vtp[a0 + 8]          = __float2bfloat16(v10);
                vtp[a0 + N_TOK + 8]  = __float2bfloat16(v11);
            }
        }
    }
    gdc_launch();
}

// ---------------- bf16 mma flash attention: split-KV, register-P, smem dist -----
__global__ void __launch_bounds__(256) attn_bf16(
        const __nv_bfloat16* __restrict__ qp, const __nv_bfloat16* __restrict__ kp,
        const __nv_bfloat16* __restrict__ vtp, const __nv_bfloat16* __restrict__ db,
        const float* __restrict__ w_edge, __half* __restrict__ out) {
    gdc_wait();
    extern __shared__ char smb[];
    const uint32_t S0 = (uint32_t)__cvta_generic_to_shared(smb);
    const uint32_t OKS = S0, OVS = S0 + 16384, OPS = S0 + 32768;
    const uint32_t ODS = S0 + 40960;

    const int b = blockIdx.z, h = blockIdx.y, n0 = blockIdx.x * 64;
    const int bh = b * HEADS + h;
    const int tid = threadIdx.x, warp = tid >> 5, lane = tid & 31;
    const int kgrp = warp >> 2, wq = warp & 3;
    const int g = lane >> 2, t = lane & 3;
    const int l7 = lane & 7, sel = lane >> 3;
    const float we2 = w_edge[2 * HEADS + h] * LOG2E;

    const uint32_t bone = (lane < 4) ? 0x3F803F80u : 0u;
    const uint32_t bones[2] = {bone, bone};

    auto issue = [&](int buf, int m0) {
        #pragma unroll
        for (int u = 0; u < 2; u++) {
            int f = tid + u * 256; int r = f >> 3; int c = f & 7;
            uint32_t off = (uint32_t)(buf * 8192 + r * 128 + ((c ^ (r & 7)) << 4));
            cp16(OKS + off, kp  + (size_t)(bh * N_TOK + m0 + r) * 64 + c * 8);
            cp16(OVS + off, vtp + (size_t)(bh * 64 + r) * N_TOK + m0 + c * 8);
            cp16(ODS + off, db  + (size_t)(b * N_TOK + n0 + r) * N_TOK + m0 + c * 8);
        }
    };

    issue(0, 0);
    #pragma unroll
    for (int u = 0; u < 2; u++) {
        int f = tid + u * 256; int r = f >> 3; int c = f & 7;
        cp16(OPS + (uint32_t)(r * 128 + ((c ^ (r & 7)) << 4)),
             qp + (size_t)(b * N_TOK + n0 + r) * D_MODEL + h * 64 + c * 8);
    }
    cp_commit();
    cp_wait<0>();
    __syncthreads();

    uint32_t Qf[4][4];
    {
        const int row = wq * 16 + l7 + ((sel & 1) << 3);
        #pragma unroll
        for (int ks = 0; ks < 4; ks++) {
            int chunk = 2 * ks + (sel >> 1);
            ldmx4(Qf[ks], OPS + (uint32_t)(row * 128 + ((chunk ^ (row & 7)) << 4)));
        }
    }

    float O[8][4];
    #pragma unroll
    for (int nt = 0; nt < 8; nt++)
        #pragma unroll
        for (int e = 0; e < 4; e++) O[nt][e] = 0.0f;
    float Ox[4] = {0.0f, 0.0f, 0.0f, 0.0f};

    const char* Dbase = smb + 40960;
    const int drow0 = (wq * 16 + g) * 128;
    const int drow1 = (wq * 16 + g + 8) * 128;

    for (int it = 0; it < 16; it++) {
        const int buf = it & 1;
        if (it + 1 < 16) { issue(buf ^ 1, (it + 1) * 64); cp_commit(); cp_wait<1>(); }
        else cp_wait<0>();
        __syncthreads();

        const char* Dsb = Dbase + buf * 8192;

        float S[4][4];
        #pragma unroll
        for (int nt = 0; nt < 4; nt++)
            #pragma unroll
            for (int e = 0; e < 4; e++) S[nt][e] = 0.0f;
        #pragma unroll
        for (int ks = 0; ks < 4; ks++) {
            #pragma unroll
            for (int np = 0; np < 2; np++) {
                uint32_t Kf[4];
                int row = kgrp * 32 + np * 16 + l7 + ((sel >> 1) << 3);
                int chunk = 2 * ks + (sel & 1);
                ldmx4(Kf, OKS + (uint32_t)(buf * 8192 + row * 128 +
                                           ((chunk ^ (row & 7)) << 4)));
                mma_bf16(S[2 * np],     Qf[ks], Kf);
                mma_bf16(S[2 * np + 1], Qf[ks], Kf + 2);
            }
        }

        uint32_t Pp[4][2];
        #pragma unroll
        for (int nt = 0; nt < 4; nt++) {
            int w = kgrp * 16 + nt * 4 + t;
            uint32_t woff = (uint32_t)((w ^ (g << 2)) << 2);
            uint32_t u0 = *(const uint32_t*)(Dsb + drow0 + woff);
            uint32_t u1 = *(const uint32_t*)(Dsb + drow1 + woff);
            float d00 = __uint_as_float(u0 << 16);
            float d01 = __uint_as_float(u0 & 0xffff0000u);
            float d10 = __uint_as_float(u1 << 16);
            float d11 = __uint_as_float(u1 & 0xffff0000u);
            Pp[nt][0] = ex2bf(pkbf(fmaf(d00, we2, S[nt][0]),
                                   fmaf(d01, we2, S[nt][1])));
            Pp[nt][1] = ex2bf(pkbf(fmaf(d10, we2, S[nt][2]),
                                   fmaf(d11, we2, S[nt][3])));
        }

        #pragma unroll
        for (int kk = 0; kk < 2; kk++) {
            uint32_t Pa[4] = {Pp[2 * kk][0], Pp[2 * kk][1],
                              Pp[2 * kk + 1][0], Pp[2 * kk + 1][1]};
            #pragma unroll
            for (int dp = 0; dp < 4; dp++) {
                uint32_t Vf[4];
                int row = dp * 16 + l7 + ((sel >> 1) << 3);
                int chunk = kgrp * 4 + 2 * kk + (sel & 1);
                ldmx4(Vf, OVS + (uint32_t)(buf * 8192 + row * 128 +
                                           ((chunk ^ (row & 7)) << 4)));
                mma_bf16(O[2 * dp],     Pa, Vf);
                mma_bf16(O[2 * dp + 1], Pa, Vf + 2);
            }
            mma_bf16(Ox, Pa, bones);
        }
        __syncthreads();
    }

    float* mbuf = (float*)smb;
    const int slot = wq * 32 + lane;
    if (kgrp) {
        #pragma unroll
        for (int nt = 0; nt < 8; nt++)
            #pragma unroll
            for (int e = 0; e < 4; e++)
                mbuf[(nt * 4 + e) * 128 + slot] = O[nt][e];
        mbuf[32 * 128 + slot] = Ox[0];
        mbuf[33 * 128 + slot] = Ox[2];
    }
    __syncthreads();
    if (!kgrp) {
        #pragma unroll
        for (int nt = 0; nt < 8; nt++)
            #pragma unroll
            for (int e = 0; e < 4; e++)
                O[nt][e] += mbuf[(nt * 4 + e) * 128 + slot];
        float ox0 = Ox[0] + mbuf[32 * 128 + slot];
        float ox2 = Ox[2] + mbuf[33 * 128 + slot];
        const int src = lane & 28;
        const float l0 = __shfl_sync(0xffffffffu, ox0, src);
        const float l1 = __shfl_sync(0xffffffffu, ox2, src);
        const float i0 = 1.0f / l0, i1 = 1.0f / l1;
        #pragma unroll
        for (int nt = 0; nt < 8; nt++) {
            int col = h * 64 + nt * 8 + 2 * t;
            size_t r0 = (size_t)(b * N_TOK + n0 + wq * 16 + g) * D_MODEL + col;
            *(uint32_t*)(out + r0)               = pkhf(O[nt][0] * i0, O[nt][1] * i0);
            *(uint32_t*)(out + r0 + 8 * D_MODEL) = pkhf(O[nt][2] * i1, O[nt][3] * i1);
        }
    }
    gdc_launch();
}

// ---------------- launch ---------------------------------------------------------
template<typename F, typename... Args>
static void launch_pdl(F func, dim3 grid, dim3 block, size_t smem, Args... args) {
    cudaLaunchConfig_t cfg = {};
    cudaLaunchAttribute at[1];
    at[0].id = cudaLaunchAttributeProgrammaticStreamSerialization;
    at[0].val.programmaticStreamSerializationAllowed = 1;
    cfg.gridDim = grid;
    cfg.blockDim = block;
    cfg.dynamicSmemBytes = smem;
    cfg.stream = 0;
    cfg.attrs = at;
    cfg.numAttrs = 1;
    cudaLaunchKernelEx(&cfg, func, args...);
}

extern "C" void kernel_launch(void* const* d_in, const int* in_sizes, int n_in,
                              void* d_out, int out_size) {
    const float* x      = (const float*)d_in[0];
    const float* coords = (const float*)d_in[1];
    const float* ln1g = (const float*)d_in[3];
    const float* ln1b = (const float*)d_in[4];
    const float* wqkv = (const float*)d_in[5];
    const float* bqkv = (const float*)d_in[6];
    const float* wedge= (const float*)d_in[7];
    const float* wout = (const float*)d_in[8];
    const float* bout = (const float*)d_in[9];
    const float* ln2g = (const float*)d_in[10];
    const float* ln2b = (const float*)d_in[11];
    const float* w1   = (const float*)d_in[12];
    const float* b1   = (const float*)d_in[13];
    const float* w2   = (const float*)d_in[14];
    const float* b2   = (const float*)d_in[15];
    float* out = (float*)d_out;

    void *p;
    float *x2;
    __half *xln16, *att16, *hid16, *wqkv_t, *wout_t, *w1_t, *w2_t;
    __nv_bfloat16 *qp, *kp, *vtp, *db;
    cudaGetSymbolAddress(&p, g_xln16);  xln16  = (__half*)p;
    cudaGetSymbolAddress(&p, g_qp);     qp     = (__nv_bfloat16*)p;
    cudaGetSymbolAddress(&p, g_kp);     kp     = (__nv_bfloat16*)p;
    cudaGetSymbolAddress(&p, g_vtp);    vtp    = (__nv_bfloat16*)p;
    cudaGetSymbolAddress(&p, g_db);     db     = (__nv_bfloat16*)p;
    cudaGetSymbolAddress(&p, g_att16);  att16  = (__half*)p;
    cudaGetSymbolAddress(&p, g_x2);     x2     = (float*)p;
    cudaGetSymbolAddress(&p, g_hid16);  hid16  = (__half*)p;
    cudaGetSymbolAddress(&p, g_wqkv_t); wqkv_t = (__half*)p;
    cudaGetSymbolAddress(&p, g_wout_t); wout_t = (__half*)p;
    cudaGetSymbolAddress(&p, g_w1_t);   w1_t   = (__half*)p;
    cudaGetSymbolAddress(&p, g_w2_t);   w2_t   = (__half*)p;

    const int ATTN_SMEM  = 57344;
    const int G16_SMEM_L = 3 * (128 * 128 + 8192);   // 73728
    const int G16_SMEM_S = 3 * (64 * 128 + 8192);    // 49152
    cudaFuncSetAttribute(attn_bf16, cudaFuncAttributeMaxDynamicSharedMemorySize, ATTN_SMEM);
    cudaFuncSetAttribute(gemm_qkv,  cudaFuncAttributeMaxDynamicSharedMemorySize, G16_SMEM_L);
    cudaFuncSetAttribute(gemm_f16<128,1>, cudaFuncAttributeMaxDynamicSharedMemorySize, G16_SMEM_L);
    cudaFuncSetAttribute(gemm_f16<64,0>,  cudaFuncAttributeMaxDynamicSharedMemorySize, G16_SMEM_S);

    // 0) prep: weight pack + LN1 + pairwise dist
    launch_pdl(prep_kernel, dim3(768 + 2048 + 2048), dim3(256), 0,
               wqkv, wout, w1, w2, wqkv_t, wout_t, w1_t, w2_t,
               x, ln1g, ln1b, xln16, coords, db);
    // 1) QKV fp16 GEMM + fused bf16 pack
    launch_pdl(gemm_qkv, dim3(1536/64, M_ROWS/128), dim3(128), (size_t)G16_SMEM_L,
               (const __half*)xln16, (const __half*)wqkv_t, bqkv, qp, kp, vtp, 1536, D_MODEL);
    // 2) attention
    launch_pdl(attn_bf16, dim3(N_TOK/64, HEADS, BATCH), dim3(256), (size_t)ATTN_SMEM,
               (const __nv_bfloat16*)qp, (const __nv_bfloat16*)kp,
               (const __nv_bfloat16*)vtp, (const __nv_bfloat16*)db, wedge, att16);
    // 3) out proj + residual(token_embs)
    launch_pdl(gemm_f16<64,0>, dim3(D_MODEL/64, M_ROWS/64), dim3(128), (size_t)G16_SMEM_S,
               (const __half*)att16, (const __half*)wout_t, bout, x, (void*)x2,
               M_ROWS, D_MODEL, D_MODEL, 0);
    // 4) LN2
    launch_pdl(ln_kernel, dim3(M_ROWS), dim3(256), 0,
               (const float*)x2, ln2g, ln2b, xln16);
    // 5) fc1 + gelu
    launch_pdl(gemm_f16<128,1>, dim3(HIDDEN/64, M_ROWS/128), dim3(128), (size_t)G16_SMEM_L,
               (const __half*)xln16, (const __half*)w1_t, b1, (const float*)nullptr,
               (void*)hid16, M_ROWS, HIDDEN, D_MODEL, 1);
    // 6) fc2 + residual(x2) -> out
    launch_pdl(gemm_f16<64,0>, dim3(D_MODEL/64, M_ROWS/64), dim3(128), (size_t)G16_SMEM_S,
               (const __half*)hid16, (const __half*)w2_t, b2, (const float*)x2,
               (void*)out, M_ROWS, D_MODEL, HIDDEN, 0);
}